// round 11
// baseline (speedup 1.0000x reference)
#include <cuda_runtime.h>
#include <cuda_bf16.h>
#include <math.h>
#include <stdint.h>

typedef unsigned long long u64;

#define BDIM 128
#define LDIM 128
#define NNEI 6
#define FAA 39
#define FBB 10
#define FC 49
#define DD 200
#define D2 400
#define D3 600
#define RR 3
#define TTI 2
#define MBOND 256
#define NEGV -9e8f
#define NATOM (BDIM*LDIM)    /* 16384 */
#define NROWN (NATOM*NNEI)   /* 98304 */
#define KPAD 64
#define KP 224               /* padded K for weight buffers */
#define KPW (KP/2)           /* packed pairs per row = 112 */
#define NDB 5                /* d-blocks per GRU CTA */
#define BNR (NDB*24)         /* B rows per GRU CTA = 120 */

// ---------------- device scratch (static, no allocation) ----------------
__device__ float g_atomfeat[NATOM*DD];   // h ping
__device__ float g_hB[NATOM*DD];         // h pong
__device__ float g_atompad[NATOM*KPAD];
__device__ float g_cur[NATOM*DD];
__device__ float g_ctx[NATOM*DD];
__device__ float g_wsum[NATOM*DD];
__device__ float g_wtot[NATOM];
__device__ float g_concat[NROWN*KPAD];
__device__ float g_nei0[NROWN*DD];
__device__ float g_s2[NATOM];
__device__ float g_mol[BDIM*DD];
__device__ float g_mol2[BDIM*DD];
__device__ float g_actmol[BDIM*DD];
__device__ float g_mwsum[BDIM*DD];
__device__ float g_mwtot[BDIM];
__device__ float g_mctx[BDIM*DD];
// packed bf16-pair weights (hi and lo planes)
__device__ uint32_t g_WT_atom_h[200*KPW],  g_WT_atom_l[200*KPW];
__device__ uint32_t g_WT_nei_h[200*KPW],   g_WT_nei_l[200*KPW];
__device__ uint32_t g_WT_att_h[3*200*KPW], g_WT_att_l[3*200*KPW];
__device__ uint32_t g_WT_molatt_h[200*KPW],g_WT_molatt_l[200*KPW];
// GRU weights: gate-interleaved rows n' = dblock*24 + gate*8 + dlow
__device__ uint32_t g_Wih_h[3*600*KPW],    g_Wih_l[3*600*KPW];
__device__ uint32_t g_Whh_h[3*600*KPW],    g_Whh_l[3*600*KPW];
__device__ uint32_t g_mWih_h[600*KPW],     g_mWih_l[600*KPW];
__device__ uint32_t g_mWhh_h[600*KPW],     g_mWhh_l[600*KPW];

// ---------------- helpers ----------------
__device__ __forceinline__ float warpsum(float v) {
    #pragma unroll
    for (int o = 16; o > 0; o >>= 1) v += __shfl_down_sync(0xffffffffu, v, o);
    return v;
}
__device__ __forceinline__ float lrelu(float x) { return x > 0.f ? x : 0.01f * x; }
__device__ __forceinline__ float eluf(float x)  { return x > 0.f ? x : expm1f(x); }
__device__ __forceinline__ float sigm(float x)  { return 1.f / (1.f + expf(-x)); }

__device__ __forceinline__ void split_bf16(float x, __nv_bfloat16& h, __nv_bfloat16& l) {
    h = __float2bfloat16_rn(x);
    l = __float2bfloat16_rn(x - __bfloat162float(h));
}
__device__ __forceinline__ uint32_t pack2(__nv_bfloat16 a, __nv_bfloat16 b) {
    __nv_bfloat162 p = __halves2bfloat162(a, b);
    return *reinterpret_cast<uint32_t*>(&p);
}

#define MMAB(c, a, b) \
    asm volatile("mma.sync.aligned.m16n8k16.row.col.f32.bf16.bf16.f32 " \
        "{%0,%1,%2,%3}, {%4,%5,%6,%7}, {%8,%9}, {%0,%1,%2,%3};" \
        : "+f"((c)[0]), "+f"((c)[1]), "+f"((c)[2]), "+f"((c)[3]) \
        : "r"((a)[0]), "r"((a)[1]), "r"((a)[2]), "r"((a)[3]), \
          "r"((b)[0]), "r"((b)[1]))

// =====================================================================
// Split-bf16 tensor GEMM (validated R8 kernel, unchanged)
// =====================================================================
__global__ __launch_bounds__(256) void bfgemm_kernel(
    const float* __restrict__ A, int lda, int K,
    const uint32_t* __restrict__ WTh, const uint32_t* __restrict__ WTl,
    const float* __restrict__ bias,
    const float* __restrict__ rowscale,
    float* __restrict__ C, int M, int Ntot, int act)
{
    __shared__ uint32_t APh[8][132], APl[8][132];
    __shared__ uint32_t BPh[8][72],  BPl[8][72];

    const int tid = threadIdx.x;
    const int wid = tid >> 5;
    const int lane = tid & 31;
    const int gid = lane >> 2;
    const int tg = lane & 3;
    const int bm0 = blockIdx.x * 128;
    const int bn0 = blockIdx.y * 64;
    const int wm = (wid & 3) * 32;
    const int wn = (wid >> 2) * 32;

    float c[2][4][4];
    #pragma unroll
    for (int mt = 0; mt < 2; mt++)
        #pragma unroll
        for (int nt = 0; nt < 4; nt++)
            #pragma unroll
            for (int q = 0; q < 4; q++) c[mt][nt][q] = 0.f;

    const int nch = (K + 15) >> 4;
    for (int chn = 0; chn < nch; chn++) {
        const int k0 = chn << 4;
        #pragma unroll
        for (int it = 0; it < 2; it++) {
            int i = tid + it * 256;
            int r = i >> 2, c4 = (i & 3) << 2;
            int k = k0 + c4;
            float4 v = make_float4(0.f, 0.f, 0.f, 0.f);
            if (k < K) v = *reinterpret_cast<const float4*>(A + (size_t)(bm0 + r) * lda + k);
            __nv_bfloat16 h0, l0, h1, l1, h2, l2, h3, l3;
            split_bf16(v.x, h0, l0); split_bf16(v.y, h1, l1);
            split_bf16(v.z, h2, l2); split_bf16(v.w, h3, l3);
            int kp = c4 >> 1;
            APh[kp][r]     = pack2(h0, h1);
            APh[kp + 1][r] = pack2(h2, h3);
            APl[kp][r]     = pack2(l0, l1);
            APl[kp + 1][r] = pack2(l2, l3);
        }
        {
            int r = tid >> 2, kp2 = (tid & 3) << 1;
            int n = bn0 + r;
            uint2 vh = make_uint2(0u, 0u), vl = make_uint2(0u, 0u);
            if (n < Ntot) {
                size_t off = (size_t)n * KPW + (k0 >> 1) + kp2;
                vh = *reinterpret_cast<const uint2*>(WTh + off);
                vl = *reinterpret_cast<const uint2*>(WTl + off);
            }
            BPh[kp2][r] = vh.x; BPh[kp2 + 1][r] = vh.y;
            BPl[kp2][r] = vl.x; BPl[kp2 + 1][r] = vl.y;
        }
        __syncthreads();

        uint32_t ah[2][4], al[2][4];
        #pragma unroll
        for (int mt = 0; mt < 2; mt++) {
            int mr = wm + mt * 16;
            ah[mt][0] = APh[tg][mr + gid];
            ah[mt][1] = APh[tg][mr + gid + 8];
            ah[mt][2] = APh[tg + 4][mr + gid];
            ah[mt][3] = APh[tg + 4][mr + gid + 8];
            al[mt][0] = APl[tg][mr + gid];
            al[mt][1] = APl[tg][mr + gid + 8];
            al[mt][2] = APl[tg + 4][mr + gid];
            al[mt][3] = APl[tg + 4][mr + gid + 8];
        }
        uint32_t bh[4][2], bl[4][2];
        #pragma unroll
        for (int nt = 0; nt < 4; nt++) {
            int nc = wn + nt * 8 + gid;
            bh[nt][0] = BPh[tg][nc];
            bh[nt][1] = BPh[tg + 4][nc];
            bl[nt][0] = BPl[tg][nc];
            bl[nt][1] = BPl[tg + 4][nc];
        }
        #pragma unroll
        for (int mt = 0; mt < 2; mt++)
            #pragma unroll
            for (int nt = 0; nt < 4; nt++) {
                MMAB(c[mt][nt], ah[mt], bh[nt]);
                MMAB(c[mt][nt], ah[mt], bl[nt]);
                MMAB(c[mt][nt], al[mt], bh[nt]);
            }
        __syncthreads();
    }

    #pragma unroll
    for (int mt = 0; mt < 2; mt++) {
        #pragma unroll
        for (int half = 0; half < 2; half++) {
            int m = bm0 + wm + mt * 16 + gid + half * 8;
            float rs = rowscale ? rowscale[m] : 1.f;
            float* crow = C + (size_t)m * Ntot;
            #pragma unroll
            for (int nt = 0; nt < 4; nt++) {
                int n = bn0 + wn + nt * 8 + 2 * tg;
                float v0 = c[mt][nt][half * 2 + 0];
                float v1 = c[mt][nt][half * 2 + 1];
                if (n < Ntot) {
                    float v = v0 + rs * (bias ? bias[n] : 0.f);
                    if (act == 1) v = lrelu(v);
                    else if (act == 2) v = eluf(v);
                    crow[n] = v;
                }
                if (n + 1 < Ntot) {
                    float v = v1 + rs * (bias ? bias[n + 1] : 0.f);
                    if (act == 1) v = lrelu(v);
                    else if (act == 2) v = eluf(v);
                    crow[n + 1] = v;
                }
            }
        }
    }
}

// =====================================================================
// Fused GRU GEMM v2: NDB=5 d-blocks (120 gate-interleaved cols) per CTA.
// grid=(M/128, 5). A tiles (X and Hin) staged once per CTA per chunk,
// amortized over 15 ntiles x 2 matrices x 3 MMAs = 90 MMAs/warp/chunk.
// Epilogue applies GRU nonlinearity; writes hOut and actOut (relu).
// =====================================================================
__global__ __launch_bounds__(256) void gru_gemm_kernel(
    const float* __restrict__ X, const float* __restrict__ Hin, int M,
    const uint32_t* __restrict__ Wih_h, const uint32_t* __restrict__ Wih_l,
    const uint32_t* __restrict__ Whh_h, const uint32_t* __restrict__ Whh_l,
    const float* __restrict__ bih, const float* __restrict__ bhh,
    float* __restrict__ hOut, float* __restrict__ actOut)
{
    __shared__ uint32_t XPh[8][132], XPl[8][132], HPh[8][132], HPl[8][132];
    __shared__ uint32_t BIh[8][BNR], BIl[8][BNR], BHh[8][BNR], BHl[8][BNR];

    const int tid = threadIdx.x;
    const int wid = tid >> 5;
    const int lane = tid & 31;
    const int gid = lane >> 2;
    const int tg = lane & 3;
    const int bm0 = blockIdx.x * 128;
    const int nrow0 = blockIdx.y * BNR;
    const int wm = wid * 16;

    float ci[3 * NDB][4], chh[3 * NDB][4];
    #pragma unroll
    for (int nt = 0; nt < 3 * NDB; nt++)
        #pragma unroll
        for (int q = 0; q < 4; q++) { ci[nt][q] = 0.f; chh[nt][q] = 0.f; }

    const int nch = 13;  // K=200 -> 13 chunks of 16
    for (int chn = 0; chn < nch; chn++) {
        const int k0 = chn << 4;
        // stage X and Hin tiles: 128 rows x 16 k each
        #pragma unroll
        for (int it = 0; it < 2; it++) {
            int i = tid + it * 256;
            int r = i >> 2, c4 = (i & 3) << 2;
            int k = k0 + c4;
            int gr = bm0 + r;
            bool ok = (gr < M) && (k < DD);
            float4 vx = make_float4(0.f, 0.f, 0.f, 0.f);
            float4 vh = make_float4(0.f, 0.f, 0.f, 0.f);
            if (ok) {
                vx = *reinterpret_cast<const float4*>(X + (size_t)gr * DD + k);
                vh = *reinterpret_cast<const float4*>(Hin + (size_t)gr * DD + k);
            }
            int kp = c4 >> 1;
            __nv_bfloat16 h0, l0, h1, l1, h2, l2, h3, l3;
            split_bf16(vx.x, h0, l0); split_bf16(vx.y, h1, l1);
            split_bf16(vx.z, h2, l2); split_bf16(vx.w, h3, l3);
            XPh[kp][r] = pack2(h0, h1); XPh[kp + 1][r] = pack2(h2, h3);
            XPl[kp][r] = pack2(l0, l1); XPl[kp + 1][r] = pack2(l2, l3);
            split_bf16(vh.x, h0, l0); split_bf16(vh.y, h1, l1);
            split_bf16(vh.z, h2, l2); split_bf16(vh.w, h3, l3);
            HPh[kp][r] = pack2(h0, h1); HPh[kp + 1][r] = pack2(h2, h3);
            HPl[kp][r] = pack2(l0, l1); HPl[kp + 1][r] = pack2(l2, l3);
        }
        // stage B tiles: BNR rows x 8 kpairs, 4 planes
        for (int i = tid; i < BNR * 8; i += 256) {
            int r = i >> 3, kp = i & 7;
            size_t off = (size_t)(nrow0 + r) * KPW + (k0 >> 1) + kp;
            BIh[kp][r] = Wih_h[off];
            BIl[kp][r] = Wih_l[off];
            BHh[kp][r] = Whh_h[off];
            BHl[kp][r] = Whh_l[off];
        }
        __syncthreads();

        uint32_t xh[4], xl[4], hh[4], hl[4];
        xh[0] = XPh[tg][wm + gid];     xh[1] = XPh[tg][wm + gid + 8];
        xh[2] = XPh[tg + 4][wm + gid]; xh[3] = XPh[tg + 4][wm + gid + 8];
        xl[0] = XPl[tg][wm + gid];     xl[1] = XPl[tg][wm + gid + 8];
        xl[2] = XPl[tg + 4][wm + gid]; xl[3] = XPl[tg + 4][wm + gid + 8];
        hh[0] = HPh[tg][wm + gid];     hh[1] = HPh[tg][wm + gid + 8];
        hh[2] = HPh[tg + 4][wm + gid]; hh[3] = HPh[tg + 4][wm + gid + 8];
        hl[0] = HPl[tg][wm + gid];     hl[1] = HPl[tg][wm + gid + 8];
        hl[2] = HPl[tg + 4][wm + gid]; hl[3] = HPl[tg + 4][wm + gid + 8];

        #pragma unroll
        for (int nt = 0; nt < 3 * NDB; nt++) {
            int nc = nt * 8 + gid;
            uint32_t bi_h[2] = { BIh[tg][nc], BIh[tg + 4][nc] };
            uint32_t bi_l[2] = { BIl[tg][nc], BIl[tg + 4][nc] };
            uint32_t bh_h[2] = { BHh[tg][nc], BHh[tg + 4][nc] };
            uint32_t bh_l[2] = { BHl[tg][nc], BHl[tg + 4][nc] };
            MMAB(ci[nt], xh, bi_h);
            MMAB(ci[nt], xh, bi_l);
            MMAB(ci[nt], xl, bi_h);
            MMAB(chh[nt], hh, bh_h);
            MMAB(chh[nt], hh, bh_l);
            MMAB(chh[nt], hl, bh_h);
        }
        __syncthreads();
    }

    // GRU epilogue
    #pragma unroll
    for (int half = 0; half < 2; half++) {
        int m = bm0 + wm + gid + half * 8;
        if (m >= M) continue;
        #pragma unroll
        for (int g = 0; g < NDB; g++) {
            #pragma unroll
            for (int q = 0; q < 2; q++) {
                int d = (blockIdx.y * NDB + g) * 8 + 2 * tg + q;
                int ix = half * 2 + q;
                float ir = ci[3 * g][ix] + bih[d];
                float hr = chh[3 * g][ix] + bhh[d];
                float iz = ci[3 * g + 1][ix] + bih[DD + d];
                float hz = chh[3 * g + 1][ix] + bhh[DD + d];
                float inn = ci[3 * g + 2][ix] + bih[2 * DD + d];
                float hnv = chh[3 * g + 2][ix] + bhh[2 * DD + d];
                float r = sigm(ir + hr);
                float z = sigm(iz + hz);
                float nv = tanhf(inn + r * hnv);
                float hv = Hin[(size_t)m * DD + d];
                float hn = (1.f - z) * nv + z * hv;
                hOut[(size_t)m * DD + d] = hn;
                actOut[(size_t)m * DD + d] = hn > 0.f ? hn : 0.f;
            }
        }
    }
}

// ---------------- weight prep: GRU [R,3D,D] -> gate-interleaved packed ----------------
__global__ void prep_gru_bf(const float* __restrict__ in,
                            uint32_t* __restrict__ outh, uint32_t* __restrict__ outl,
                            int R)
{
    int i = blockIdx.x * 256 + threadIdx.x;
    if (i >= R * D3 * KPW) return;
    int kp = i % KPW;
    int rn = i / KPW;
    int np = rn % D3;
    int r = rn / D3;
    int dblk = np / 24, rem = np % 24;
    int gate = rem >> 3, dlow = rem & 7;
    int orow = gate * DD + dblk * 8 + dlow;
    int k = kp << 1;
    float x0 = (k < DD) ? in[((size_t)r * D3 + orow) * DD + k] : 0.f;
    float x1 = (k + 1 < DD) ? in[((size_t)r * D3 + orow) * DD + k + 1] : 0.f;
    __nv_bfloat16 h0, l0, h1, l1;
    split_bf16(x0, h0, l0); split_bf16(x1, h1, l1);
    outh[i] = pack2(h0, h1);
    outl[i] = pack2(l0, l1);
}

// ---------------- weight prep: [R,K,N] -> packed hi/lo [R,N,KPW] ----------------
__global__ void prep_trans_bf(const float* __restrict__ in,
                              uint32_t* __restrict__ outh, uint32_t* __restrict__ outl,
                              int R, int K, int N)
{
    int i = blockIdx.x * 256 + threadIdx.x;
    if (i >= R * N * KPW) return;
    int kp = i % KPW;
    int rn = i / KPW;
    int n = rn % N;
    int r = rn / N;
    int k = kp << 1;
    float x0 = (k < K) ? in[((size_t)r * K + k) * N + n] : 0.f;
    float x1 = (k + 1 < K) ? in[((size_t)r * K + k + 1) * N + n] : 0.f;
    __nv_bfloat16 h0, l0, h1, l1;
    split_bf16(x0, h0, l0); split_bf16(x1, h1, l1);
    outh[i] = pack2(h0, h1);
    outl[i] = pack2(l0, l1);
}

// ---------------- pad atom_list [NATOM,39] -> [NATOM,64] ----------------
__global__ void pad_atom_kernel(const float* __restrict__ atom_list, float* __restrict__ out)
{
    int i = blockIdx.x * blockDim.x + threadIdx.x;
    if (i >= NATOM * KPAD) return;
    int row = i >> 6;
    int f = i & 63;
    out[i] = (f < FAA) ? atom_list[row * FAA + f] : 0.f;
}

// ---------------- build concat(atom_nei, bond_nei) [NROWN, 64] padded ----------------
__global__ void build_concat(const float* __restrict__ atom_list,
                             const float* __restrict__ bond_list,
                             const int* __restrict__ adeg,
                             const int* __restrict__ bdeg,
                             float* __restrict__ out)
{
    int i = blockIdx.x * blockDim.x + threadIdx.x;
    if (i >= NROWN * KPAD) return;
    int row = i >> 6;
    int f = i & 63;
    int b = row / (LDIM * NNEI);
    float v = 0.f;
    if (f < FAA) {
        int a = adeg[row];
        v = atom_list[((size_t)b * LDIM + a) * FAA + f];
    } else if (f < FC) {
        int bd = bdeg[row];
        v = bond_list[((size_t)b * MBOND + bd) * FBB + (f - FAA)];
    }
    out[i] = v;
}

// ---------------- attention: softmax weights + weighted neighbor sum ----------------
__global__ void ctx_kernel(const float* __restrict__ cur,
                           const float* __restrict__ neiBuf,
                           const int* __restrict__ adeg,
                           const float* __restrict__ Wal,
                           const float* __restrict__ bal,
                           float* __restrict__ wsum,
                           float* __restrict__ wtot,
                           int firstRound)
{
    const int atom = blockIdx.x;
    const int b = atom / LDIM;
    const int tid = threadIdx.x;
    const int lane = tid & 31;

    __shared__ float curS[DD];
    __shared__ float neiS[NNEI][DD];
    __shared__ float red[NNEI + 1];
    __shared__ int idxS[NNEI];

    if (tid <= NNEI) red[tid] = 0.f;
    if (tid < NNEI) idxS[tid] = adeg[atom * NNEI + tid];
    for (int d = tid; d < DD; d += 256) curS[d] = cur[(size_t)atom * DD + d];
    __syncthreads();

    #pragma unroll
    for (int n = 0; n < NNEI; n++) {
        const float* src = firstRound ? (neiBuf + ((size_t)atom * NNEI + n) * DD)
                                      : (cur + ((size_t)(b * LDIM + idxS[n])) * DD);
        for (int d = tid; d < DD; d += 256) neiS[n][d] = src[d];
    }
    __syncthreads();

    float p[NNEI + 1];
    #pragma unroll
    for (int n = 0; n <= NNEI; n++) p[n] = 0.f;
    for (int d = tid; d < DD; d += 256) {
        float a1 = Wal[d];
        float a2 = Wal[DD + d];
        p[NNEI] += a1 * curS[d];
        #pragma unroll
        for (int n = 0; n < NNEI; n++) p[n] += a2 * neiS[n][d];
    }
    #pragma unroll
    for (int n = 0; n <= NNEI; n++) {
        float s = warpsum(p[n]);
        if (lane == 0) atomicAdd(&red[n], s);
    }
    __syncthreads();

    float dtop = red[NNEI];
    float bb = bal[0];
    float sc[NNEI];
    float msk[NNEI];
    float mx = -1e30f;
    #pragma unroll
    for (int n = 0; n < NNEI; n++) {
        float a = lrelu(dtop + red[n] + bb);
        bool pad = (idxS[n] == LDIM - 1);
        msk[n] = pad ? 0.f : 1.f;
        a += pad ? NEGV : 0.f;
        sc[n] = a;
        mx = fmaxf(mx, a);
    }
    float sum = 0.f;
    float w[NNEI];
    #pragma unroll
    for (int n = 0; n < NNEI; n++) { w[n] = expf(sc[n] - mx); sum += w[n]; }
    float inv = 1.f / sum;
    float wt = 0.f;
    #pragma unroll
    for (int n = 0; n < NNEI; n++) { w[n] = w[n] * inv * msk[n]; wt += w[n]; }

    for (int d = tid; d < DD; d += 256) {
        float s = 0.f;
        #pragma unroll
        for (int n = 0; n < NNEI; n++) s += w[n] * neiS[n][d];
        wsum[(size_t)atom * DD + d] = s;
    }
    if (tid == 0) wtot[atom] = wt;
}

// ---------------- mol prep: masked sum + per-atom s2 dot ----------------
__global__ void molprep_kernel(const float* __restrict__ cur, const float* __restrict__ amask,
                               const float* __restrict__ Wma,
                               float* __restrict__ mol, float* __restrict__ actmol,
                               float* __restrict__ s2)
{
    int b = blockIdx.x;
    int tid = threadIdx.x;
    for (int d = tid; d < DD; d += 256) {
        float s = 0.f;
        for (int l = 0; l < LDIM; l++)
            s += cur[((size_t)b * LDIM + l) * DD + d] * amask[b * LDIM + l];
        mol[b * DD + d] = s;
        actmol[b * DD + d] = s > 0.f ? s : 0.f;
    }
    int w = tid >> 5;
    int lane = tid & 31;
    for (int l = w; l < LDIM; l += 8) {
        float p = 0.f;
        const float* row = cur + ((size_t)b * LDIM + l) * DD;
        for (int d = lane; d < DD; d += 32) p += row[d] * Wma[DD + d];
        p = warpsum(p);
        if (lane == 0) s2[b * LDIM + l] = p;
    }
}

// ---------------- mol attention: weights + weighted atom sum ----------------
__global__ void molctx_kernel(const float* __restrict__ actmol,
                              const float* __restrict__ cur,
                              const float* __restrict__ s2,
                              const float* __restrict__ amask,
                              const float* __restrict__ Wma,
                              const float* __restrict__ bma,
                              float* __restrict__ mwsum,
                              float* __restrict__ mwtot)
{
    int b = blockIdx.x;
    int tid = threadIdx.x;
    int lane = tid & 31;
    __shared__ float redv;
    __shared__ float sc[LDIM];
    __shared__ float wS[LDIM];
    if (tid == 0) redv = 0.f;
    __syncthreads();

    float p = 0.f;
    for (int d = tid; d < DD; d += 256) p += actmol[b * DD + d] * Wma[d];
    p = warpsum(p);
    if (lane == 0) atomicAdd(&redv, p);
    __syncthreads();

    if (tid < LDIM) {
        float a = lrelu(redv + s2[b * LDIM + tid] + bma[0]);
        if (amask[b * LDIM + tid] == 0.f) a += NEGV;
        sc[tid] = a;
    }
    __syncthreads();

    float mx = -1e30f;
    for (int l = 0; l < LDIM; l++) mx = fmaxf(mx, sc[l]);
    float sum = 0.f;
    for (int l = 0; l < LDIM; l++) sum += expf(sc[l] - mx);
    float inv = 1.f / sum;
    if (tid < LDIM) wS[tid] = expf(sc[tid] - mx) * inv * amask[b * LDIM + tid];
    __syncthreads();

    for (int d = tid; d < DD; d += 256) {
        float s = 0.f;
        for (int l = 0; l < LDIM; l++)
            s += wS[l] * cur[((size_t)b * LDIM + l) * DD + d];
        mwsum[b * DD + d] = s;
    }
    if (tid == 0) {
        float wt = 0.f;
        for (int l = 0; l < LDIM; l++) wt += wS[l];
        mwtot[b] = wt;
    }
}

// ---------------- final projection ----------------
__global__ void final_kernel(const float* __restrict__ mol,
                             const float* __restrict__ Wm, const float* __restrict__ bm,
                             const float* __restrict__ Wo, const float* __restrict__ bo,
                             float* __restrict__ out)
{
    int b = blockIdx.x;
    int tid = threadIdx.x;
    int lane = tid & 31;
    __shared__ float featS[D2];
    __shared__ float ws[8];
    for (int j = tid; j < D2; j += 256)
        featS[j] = (j < DD) ? mol[b * DD + j] : (mol[b * DD + j - DD] + (float)(RR - 2));
    __syncthreads();
    float p = 0.f;
    for (int d = tid; d < DD; d += 256) {
        float s = bm[d];
        for (int j = 0; j < D2; j++) s += featS[j] * Wm[j * DD + d];
        p += s * Wo[d];
    }
    p = warpsum(p);
    if (lane == 0) ws[tid >> 5] = p;
    __syncthreads();
    if (tid == 0) {
        float t = 0.f;
        for (int i = 0; i < 8; i++) t += ws[i];
        out[b] = t + bo[0];
    }
}

// ---------------- host-side dispatch ----------------
static void tgemm(const float* A, int lda, int K,
                  const uint32_t* WTh, const uint32_t* WTl,
                  const float* bias, const float* rowscale, float* C,
                  int M, int Ntot, int act)
{
    dim3 g(M / 128, (Ntot + 63) / 64);
    bfgemm_kernel<<<g, 256>>>(A, lda, K, WTh, WTl, bias, rowscale, C, M, Ntot, act);
}

static void grugemm(const float* X, const float* Hin, int M,
                    const uint32_t* Wih_h, const uint32_t* Wih_l,
                    const uint32_t* Whh_h, const uint32_t* Whh_l,
                    const float* bih, const float* bhh,
                    float* hOut, float* actOut)
{
    dim3 g((M + 127) / 128, 5);
    gru_gemm_kernel<<<g, 256>>>(X, Hin, M, Wih_h, Wih_l, Whh_h, Whh_l,
                                bih, bhh, hOut, actOut);
}

extern "C" void kernel_launch(void* const* d_in, const int* in_sizes, int n_in,
                              void* d_out, int out_size)
{
    const float* atom_list   = (const float*)d_in[0];
    const float* bond_list   = (const float*)d_in[1];
    const int*   adeg        = (const int*)d_in[2];
    const int*   bdeg        = (const int*)d_in[3];
    const float* amask       = (const float*)d_in[4];
    const float* W_atom      = (const float*)d_in[5];
    const float* b_atom      = (const float*)d_in[6];
    const float* W_nei       = (const float*)d_in[7];
    const float* b_nei       = (const float*)d_in[8];
    const float* W_align     = (const float*)d_in[9];
    const float* b_align     = (const float*)d_in[10];
    const float* W_attend    = (const float*)d_in[11];
    const float* b_attend    = (const float*)d_in[12];
    const float* Wih         = (const float*)d_in[13];
    const float* Whh         = (const float*)d_in[14];
    const float* bih         = (const float*)d_in[15];
    const float* bhh         = (const float*)d_in[16];
    const float* W_mol_align = (const float*)d_in[17];
    const float* b_mol_align = (const float*)d_in[18];
    const float* W_mol_att   = (const float*)d_in[19];
    const float* b_mol_att   = (const float*)d_in[20];
    const float* mWih        = (const float*)d_in[21];
    const float* mWhh        = (const float*)d_in[22];
    const float* mbih        = (const float*)d_in[23];
    const float* mbhh        = (const float*)d_in[24];
    const float* W_metric    = (const float*)d_in[25];
    const float* b_metric    = (const float*)d_in[26];
    const float* W_out       = (const float*)d_in[27];
    const float* b_out       = (const float*)d_in[28];

    float *atomfeat, *hB, *atompad, *cur, *ctx, *wsum, *wtot, *concat, *nei0;
    float *s2, *mol, *mol2, *actmol, *mwsum, *mwtot, *mctx;
    uint32_t *WT_atom_h, *WT_atom_l, *WT_nei_h, *WT_nei_l, *WT_att_h, *WT_att_l;
    uint32_t *WT_molatt_h, *WT_molatt_l, *Wih_h, *Wih_l, *Whh_h, *Whh_l;
    uint32_t *mWih_h, *mWih_l, *mWhh_h, *mWhh_l;
    cudaGetSymbolAddress((void**)&atomfeat, g_atomfeat);
    cudaGetSymbolAddress((void**)&hB, g_hB);
    cudaGetSymbolAddress((void**)&atompad, g_atompad);
    cudaGetSymbolAddress((void**)&cur, g_cur);
    cudaGetSymbolAddress((void**)&ctx, g_ctx);
    cudaGetSymbolAddress((void**)&wsum, g_wsum);
    cudaGetSymbolAddress((void**)&wtot, g_wtot);
    cudaGetSymbolAddress((void**)&concat, g_concat);
    cudaGetSymbolAddress((void**)&nei0, g_nei0);
    cudaGetSymbolAddress((void**)&s2, g_s2);
    cudaGetSymbolAddress((void**)&mol, g_mol);
    cudaGetSymbolAddress((void**)&mol2, g_mol2);
    cudaGetSymbolAddress((void**)&actmol, g_actmol);
    cudaGetSymbolAddress((void**)&mwsum, g_mwsum);
    cudaGetSymbolAddress((void**)&mwtot, g_mwtot);
    cudaGetSymbolAddress((void**)&mctx, g_mctx);
    cudaGetSymbolAddress((void**)&WT_atom_h, g_WT_atom_h);
    cudaGetSymbolAddress((void**)&WT_atom_l, g_WT_atom_l);
    cudaGetSymbolAddress((void**)&WT_nei_h, g_WT_nei_h);
    cudaGetSymbolAddress((void**)&WT_nei_l, g_WT_nei_l);
    cudaGetSymbolAddress((void**)&WT_att_h, g_WT_att_h);
    cudaGetSymbolAddress((void**)&WT_att_l, g_WT_att_l);
    cudaGetSymbolAddress((void**)&WT_molatt_h, g_WT_molatt_h);
    cudaGetSymbolAddress((void**)&WT_molatt_l, g_WT_molatt_l);
    cudaGetSymbolAddress((void**)&Wih_h, g_Wih_h);
    cudaGetSymbolAddress((void**)&Wih_l, g_Wih_l);
    cudaGetSymbolAddress((void**)&Whh_h, g_Whh_h);
    cudaGetSymbolAddress((void**)&Whh_l, g_Whh_l);
    cudaGetSymbolAddress((void**)&mWih_h, g_mWih_h);
    cudaGetSymbolAddress((void**)&mWih_l, g_mWih_l);
    cudaGetSymbolAddress((void**)&mWhh_h, g_mWhh_h);
    cudaGetSymbolAddress((void**)&mWhh_l, g_mWhh_l);

    // 0) weight prep
    {
        int n;
        n = 3 * D3 * KPW; prep_gru_bf<<<(n + 255) / 256, 256>>>(Wih, Wih_h, Wih_l, 3);
        n = 3 * D3 * KPW; prep_gru_bf<<<(n + 255) / 256, 256>>>(Whh, Whh_h, Whh_l, 3);
        n = D3 * KPW;     prep_gru_bf<<<(n + 255) / 256, 256>>>(mWih, mWih_h, mWih_l, 1);
        n = D3 * KPW;     prep_gru_bf<<<(n + 255) / 256, 256>>>(mWhh, mWhh_h, mWhh_l, 1);
        n = 200 * KPW;  prep_trans_bf<<<(n + 255) / 256, 256>>>(W_atom, WT_atom_h, WT_atom_l, 1, FAA, DD);
        n = 200 * KPW;  prep_trans_bf<<<(n + 255) / 256, 256>>>(W_nei, WT_nei_h, WT_nei_l, 1, FC, DD);
        n = 3 * 200 * KPW; prep_trans_bf<<<(n + 255) / 256, 256>>>(W_attend, WT_att_h, WT_att_l, 3, DD, DD);
        n = 200 * KPW;  prep_trans_bf<<<(n + 255) / 256, 256>>>(W_mol_att, WT_molatt_h, WT_molatt_l, 1, DD, DD);
    }

    // 1) atom_feature = lrelu(atom_list @ W_atom + b_atom)
    pad_atom_kernel<<<(NATOM * KPAD + 255) / 256, 256>>>(atom_list, atompad);
    tgemm(atompad, KPAD, KPAD, WT_atom_h, WT_atom_l, b_atom, nullptr, atomfeat, NATOM, DD, 1);

    // 2) nei0 = lrelu(concat @ W_nei + b_nei)
    build_concat<<<(NROWN * KPAD + 255) / 256, 256>>>(atom_list, bond_list, adeg, bdeg, concat);
    tgemm(concat, KPAD, KPAD, WT_nei_h, WT_nei_l, b_nei, nullptr, nei0, NROWN, DD, 1);

    // 3) atom GRU rounds (h ping-pong: atomfeat -> hB -> atomfeat -> hB)
    float* hbuf[2] = { atomfeat, hB };
    for (int r = 0; r < RR; r++) {
        const float* curp = (r == 0) ? atomfeat : cur;
        float* h_in = hbuf[r & 1];
        float* h_out = hbuf[(r + 1) & 1];
        ctx_kernel<<<NATOM, 256>>>(curp, (r == 0) ? nei0 : nullptr, adeg,
                                   W_align + (size_t)r * D2, b_align + r,
                                   wsum, wtot, (r == 0) ? 1 : 0);
        tgemm(wsum, DD, DD, WT_att_h + (size_t)r * 200 * KPW, WT_att_l + (size_t)r * 200 * KPW,
              b_attend + r * DD, wtot, ctx, NATOM, DD, 2);
        grugemm(ctx, h_in, NATOM,
                Wih_h + (size_t)r * D3 * KPW, Wih_l + (size_t)r * D3 * KPW,
                Whh_h + (size_t)r * D3 * KPW, Whh_l + (size_t)r * D3 * KPW,
                bih + r * D3, bhh + r * D3, h_out, cur);
    }

    // 4) mol phase (mol ping-pong: mol -> mol2 -> mol)
    molprep_kernel<<<BDIM, 256>>>(cur, amask, W_mol_align, mol, actmol, s2);
    float* mbuf[2] = { mol, mol2 };
    for (int t = 0; t < TTI; t++) {
        float* m_in = mbuf[t & 1];
        float* m_out = mbuf[(t + 1) & 1];
        molctx_kernel<<<BDIM, 256>>>(actmol, cur, s2, amask, W_mol_align, b_mol_align,
                                     mwsum, mwtot);
        tgemm(mwsum, DD, DD, WT_molatt_h, WT_molatt_l, b_mol_att, mwtot, mctx, BDIM, DD, 2);
        grugemm(mctx, m_in, BDIM, mWih_h, mWih_l, mWhh_h, mWhh_l,
                mbih, mbhh, m_out, actmol);
    }

    // 5) final projection (TTI even -> result back in g_mol)
    final_kernel<<<BDIM, 256>>>(mol, W_metric, b_metric, W_out, b_out, (float*)d_out);
}

// round 13
// speedup vs baseline: 1.1799x; 1.1799x over previous
#include <cuda_runtime.h>
#include <cuda_bf16.h>
#include <math.h>
#include <stdint.h>

typedef unsigned long long u64;

#define BDIM 128
#define LDIM 128
#define NNEI 6
#define FAA 39
#define FBB 10
#define FC 49
#define DD 200
#define D2 400
#define D3 600
#define RR 3
#define TTI 2
#define MBOND 256
#define NEGV -9e8f
#define NATOM (BDIM*LDIM)    /* 16384 */
#define NROWN (NATOM*NNEI)   /* 98304 */
#define KPAD 64
#define KP 224               /* padded K for weight buffers */
#define KPW (KP/2)           /* packed pairs per row = 112 */

// ---------------- device scratch (static, no allocation) ----------------
__device__ float g_atomfeat[NATOM*DD];   // also serves as h (updated in place)
__device__ float g_atompad[NATOM*KPAD];
__device__ float g_cur[NATOM*DD];
__device__ float g_ctx[NATOM*DD];
__device__ float g_wsum[NATOM*DD];
__device__ float g_wtot[NATOM];
__device__ float g_concat[NROWN*KPAD];
__device__ float g_nei0[NROWN*DD];
__device__ float g_gi[NATOM*D3];
__device__ float g_gh[NATOM*D3];
__device__ float g_s2[NATOM];
__device__ float g_mol[BDIM*DD];
__device__ float g_actmol[BDIM*DD];
__device__ float g_mwsum[BDIM*DD];
__device__ float g_mwtot[BDIM];
__device__ float g_mctx[BDIM*DD];
__device__ float g_mgi[BDIM*D3];
__device__ float g_mgh[BDIM*D3];
// packed bf16-pair weights (hi and lo planes)
__device__ uint32_t g_WT_atom_h[200*KPW],  g_WT_atom_l[200*KPW];
__device__ uint32_t g_WT_nei_h[200*KPW],   g_WT_nei_l[200*KPW];
__device__ uint32_t g_WT_att_h[3*200*KPW], g_WT_att_l[3*200*KPW];
__device__ uint32_t g_WT_molatt_h[200*KPW],g_WT_molatt_l[200*KPW];
__device__ uint32_t g_Wih_h[3*600*KPW],    g_Wih_l[3*600*KPW];
__device__ uint32_t g_Whh_h[3*600*KPW],    g_Whh_l[3*600*KPW];
__device__ uint32_t g_mWih_h[600*KPW],     g_mWih_l[600*KPW];
__device__ uint32_t g_mWhh_h[600*KPW],     g_mWhh_l[600*KPW];

// ---------------- helpers ----------------
__device__ __forceinline__ float warpsum(float v) {
    #pragma unroll
    for (int o = 16; o > 0; o >>= 1) v += __shfl_down_sync(0xffffffffu, v, o);
    return v;
}
__device__ __forceinline__ float lrelu(float x) { return x > 0.f ? x : 0.01f * x; }
__device__ __forceinline__ float eluf(float x)  { return x > 0.f ? x : expm1f(x); }
__device__ __forceinline__ float sigm(float x)  { return 1.f / (1.f + expf(-x)); }

__device__ __forceinline__ void split_bf16(float x, __nv_bfloat16& h, __nv_bfloat16& l) {
    h = __float2bfloat16_rn(x);
    l = __float2bfloat16_rn(x - __bfloat162float(h));
}
__device__ __forceinline__ uint32_t pack2(__nv_bfloat16 a, __nv_bfloat16 b) {
    __nv_bfloat162 p = __halves2bfloat162(a, b);
    return *reinterpret_cast<uint32_t*>(&p);
}

#define MMAB(c, a, b) \
    asm volatile("mma.sync.aligned.m16n8k16.row.col.f32.bf16.bf16.f32 " \
        "{%0,%1,%2,%3}, {%4,%5,%6,%7}, {%8,%9}, {%0,%1,%2,%3};" \
        : "+f"((c)[0]), "+f"((c)[1]), "+f"((c)[2]), "+f"((c)[3]) \
        : "r"((a)[0]), "r"((a)[1]), "r"((a)[2]), "r"((a)[3]), \
          "r"((b)[0]), "r"((b)[1]))

// =====================================================================
// Split-bf16 tensor GEMM with register prefetch (software pipelining).
// C[M,Ntot] = act(A[M,K](lda) @ WT^T + rs[m]*bias)
// DUAL=1: blockIdx.z selects (A2, W2, bias2, C2) for a second GEMM.
// =====================================================================
template<int DUAL>
__global__ __launch_bounds__(256) void bfgemm_kernel(
    const float* __restrict__ A, int lda, int K,
    const uint32_t* __restrict__ WTh, const uint32_t* __restrict__ WTl,
    const float* __restrict__ bias,
    const float* __restrict__ rowscale,
    float* __restrict__ C, int M, int Ntot, int act,
    const float* A2, const uint32_t* W2h, const uint32_t* W2l,
    const float* bias2, float* C2)
{
    if (DUAL && blockIdx.z == 1) {
        A = A2; WTh = W2h; WTl = W2l; bias = bias2; C = C2;
    }

    __shared__ uint32_t APh[8][132], APl[8][132];
    __shared__ uint32_t BPh[8][72],  BPl[8][72];

    const int tid = threadIdx.x;
    const int wid = tid >> 5;
    const int lane = tid & 31;
    const int gid = lane >> 2;
    const int tg = lane & 3;
    const int bm0 = blockIdx.x * 128;
    const int bn0 = blockIdx.y * 64;
    const int wm = (wid & 3) * 32;
    const int wn = (wid >> 2) * 32;

    // A loader indices (2 float4 per thread), B loader (1 uint2 x 2 planes)
    const int a_r0 = tid >> 2, a_c4 = (tid & 3) << 2;
    const int b_r = tid >> 2, b_kp2 = (tid & 3) << 1;

    float c[2][4][4];
    #pragma unroll
    for (int mt = 0; mt < 2; mt++)
        #pragma unroll
        for (int nt = 0; nt < 4; nt++)
            #pragma unroll
            for (int q = 0; q < 4; q++) c[mt][nt][q] = 0.f;

    const int nch = (K + 15) >> 4;

    // prefetch chunk 0
    float4 av[2];
    uint2 bvh, bvl;
    {
        #pragma unroll
        for (int it = 0; it < 2; it++) {
            int r = a_r0 + it * 64;
            int k = a_c4;
            av[it] = (k < K) ? *reinterpret_cast<const float4*>(A + (size_t)(bm0 + r) * lda + k)
                             : make_float4(0.f, 0.f, 0.f, 0.f);
        }
        int n = bn0 + b_r;
        if (n < Ntot) {
            size_t off = (size_t)n * KPW + b_kp2;
            bvh = *reinterpret_cast<const uint2*>(WTh + off);
            bvl = *reinterpret_cast<const uint2*>(WTl + off);
        } else { bvh = make_uint2(0u, 0u); bvl = make_uint2(0u, 0u); }
    }

    for (int chn = 0; chn < nch; chn++) {
        // store staged regs -> smem (split/pack A)
        #pragma unroll
        for (int it = 0; it < 2; it++) {
            int r = a_r0 + it * 64;
            int kp = a_c4 >> 1;
            __nv_bfloat16 h0, l0, h1, l1, h2, l2, h3, l3;
            split_bf16(av[it].x, h0, l0); split_bf16(av[it].y, h1, l1);
            split_bf16(av[it].z, h2, l2); split_bf16(av[it].w, h3, l3);
            APh[kp][r]     = pack2(h0, h1);
            APh[kp + 1][r] = pack2(h2, h3);
            APl[kp][r]     = pack2(l0, l1);
            APl[kp + 1][r] = pack2(l2, l3);
        }
        BPh[b_kp2][b_r] = bvh.x; BPh[b_kp2 + 1][b_r] = bvh.y;
        BPl[b_kp2][b_r] = bvl.x; BPl[b_kp2 + 1][b_r] = bvl.y;
        __syncthreads();

        // prefetch next chunk while MMAs run
        if (chn + 1 < nch) {
            const int k0 = (chn + 1) << 4;
            #pragma unroll
            for (int it = 0; it < 2; it++) {
                int r = a_r0 + it * 64;
                int k = k0 + a_c4;
                av[it] = (k < K) ? *reinterpret_cast<const float4*>(A + (size_t)(bm0 + r) * lda + k)
                                 : make_float4(0.f, 0.f, 0.f, 0.f);
            }
            int n = bn0 + b_r;
            if (n < Ntot) {
                size_t off = (size_t)n * KPW + (k0 >> 1) + b_kp2;
                bvh = *reinterpret_cast<const uint2*>(WTh + off);
                bvl = *reinterpret_cast<const uint2*>(WTl + off);
            } else { bvh = make_uint2(0u, 0u); bvl = make_uint2(0u, 0u); }
        }

        uint32_t ah[2][4], al[2][4];
        #pragma unroll
        for (int mt = 0; mt < 2; mt++) {
            int mr = wm + mt * 16;
            ah[mt][0] = APh[tg][mr + gid];
            ah[mt][1] = APh[tg][mr + gid + 8];
            ah[mt][2] = APh[tg + 4][mr + gid];
            ah[mt][3] = APh[tg + 4][mr + gid + 8];
            al[mt][0] = APl[tg][mr + gid];
            al[mt][1] = APl[tg][mr + gid + 8];
            al[mt][2] = APl[tg + 4][mr + gid];
            al[mt][3] = APl[tg + 4][mr + gid + 8];
        }
        uint32_t bh[4][2], bl[4][2];
        #pragma unroll
        for (int nt = 0; nt < 4; nt++) {
            int nc = wn + nt * 8 + gid;
            bh[nt][0] = BPh[tg][nc];
            bh[nt][1] = BPh[tg + 4][nc];
            bl[nt][0] = BPl[tg][nc];
            bl[nt][1] = BPl[tg + 4][nc];
        }
        #pragma unroll
        for (int mt = 0; mt < 2; mt++)
            #pragma unroll
            for (int nt = 0; nt < 4; nt++) {
                MMAB(c[mt][nt], ah[mt], bh[nt]);
                MMAB(c[mt][nt], ah[mt], bl[nt]);
                MMAB(c[mt][nt], al[mt], bh[nt]);
            }
        __syncthreads();
    }

    #pragma unroll
    for (int mt = 0; mt < 2; mt++) {
        #pragma unroll
        for (int half = 0; half < 2; half++) {
            int m = bm0 + wm + mt * 16 + gid + half * 8;
            float rs = rowscale ? rowscale[m] : 1.f;
            float* crow = C + (size_t)m * Ntot;
            #pragma unroll
            for (int nt = 0; nt < 4; nt++) {
                int n = bn0 + wn + nt * 8 + 2 * tg;
                float v0 = c[mt][nt][half * 2 + 0];
                float v1 = c[mt][nt][half * 2 + 1];
                if (n < Ntot) {
                    float v = v0 + rs * (bias ? bias[n] : 0.f);
                    if (act == 1) v = lrelu(v);
                    else if (act == 2) v = eluf(v);
                    crow[n] = v;
                }
                if (n + 1 < Ntot) {
                    float v = v1 + rs * (bias ? bias[n + 1] : 0.f);
                    if (act == 1) v = lrelu(v);
                    else if (act == 2) v = eluf(v);
                    crow[n + 1] = v;
                }
            }
        }
    }
}

// ---------------- weight prep: [NT,K] row-major -> packed hi/lo [NT,KPW] ----------------
__global__ void prep_pad_bf(const float* __restrict__ in,
                            uint32_t* __restrict__ outh, uint32_t* __restrict__ outl,
                            int NT, int K)
{
    int i = blockIdx.x * 256 + threadIdx.x;
    if (i >= NT * KPW) return;
    int n = i / KPW, kp = i - n * KPW;
    int k = kp << 1;
    float x0 = (k < K) ? in[(size_t)n * K + k] : 0.f;
    float x1 = (k + 1 < K) ? in[(size_t)n * K + k + 1] : 0.f;
    __nv_bfloat16 h0, l0, h1, l1;
    split_bf16(x0, h0, l0); split_bf16(x1, h1, l1);
    outh[i] = pack2(h0, h1);
    outl[i] = pack2(l0, l1);
}

// ---------------- weight prep: [R,K,N] -> packed hi/lo [R,N,KPW] ----------------
__global__ void prep_trans_bf(const float* __restrict__ in,
                              uint32_t* __restrict__ outh, uint32_t* __restrict__ outl,
                              int R, int K, int N)
{
    int i = blockIdx.x * 256 + threadIdx.x;
    if (i >= R * N * KPW) return;
    int kp = i % KPW;
    int rn = i / KPW;
    int n = rn % N;
    int r = rn / N;
    int k = kp << 1;
    float x0 = (k < K) ? in[((size_t)r * K + k) * N + n] : 0.f;
    float x1 = (k + 1 < K) ? in[((size_t)r * K + k + 1) * N + n] : 0.f;
    __nv_bfloat16 h0, l0, h1, l1;
    split_bf16(x0, h0, l0); split_bf16(x1, h1, l1);
    outh[i] = pack2(h0, h1);
    outl[i] = pack2(l0, l1);
}

// ---------------- pad atom_list [NATOM,39] -> [NATOM,64] ----------------
__global__ void pad_atom_kernel(const float* __restrict__ atom_list, float* __restrict__ out)
{
    int i = blockIdx.x * blockDim.x + threadIdx.x;
    if (i >= NATOM * KPAD) return;
    int row = i >> 6;
    int f = i & 63;
    out[i] = (f < FAA) ? atom_list[row * FAA + f] : 0.f;
}

// ---------------- build concat(atom_nei, bond_nei) [NROWN, 64] padded ----------------
__global__ void build_concat(const float* __restrict__ atom_list,
                             const float* __restrict__ bond_list,
                             const int* __restrict__ adeg,
                             const int* __restrict__ bdeg,
                             float* __restrict__ out)
{
    int i = blockIdx.x * blockDim.x + threadIdx.x;
    if (i >= NROWN * KPAD) return;
    int row = i >> 6;
    int f = i & 63;
    int b = row / (LDIM * NNEI);
    float v = 0.f;
    if (f < FAA) {
        int a = adeg[row];
        v = atom_list[((size_t)b * LDIM + a) * FAA + f];
    } else if (f < FC) {
        int bd = bdeg[row];
        v = bond_list[((size_t)b * MBOND + bd) * FBB + (f - FAA)];
    }
    out[i] = v;
}

// ---------------- attention: softmax weights + weighted neighbor sum ----------------
__global__ void ctx_kernel(const float* __restrict__ cur,
                           const float* __restrict__ neiBuf,
                           const int* __restrict__ adeg,
                           const float* __restrict__ Wal,
                           const float* __restrict__ bal,
                           float* __restrict__ wsum,
                           float* __restrict__ wtot,
                           int firstRound)
{
    const int atom = blockIdx.x;
    const int b = atom / LDIM;
    const int tid = threadIdx.x;
    const int lane = tid & 31;

    __shared__ float curS[DD];
    __shared__ float neiS[NNEI][DD];
    __shared__ float red[NNEI + 1];
    __shared__ int idxS[NNEI];

    if (tid <= NNEI) red[tid] = 0.f;
    if (tid < NNEI) idxS[tid] = adeg[atom * NNEI + tid];
    for (int d = tid; d < DD; d += 256) curS[d] = cur[(size_t)atom * DD + d];
    __syncthreads();

    #pragma unroll
    for (int n = 0; n < NNEI; n++) {
        const float* src = firstRound ? (neiBuf + ((size_t)atom * NNEI + n) * DD)
                                      : (cur + ((size_t)(b * LDIM + idxS[n])) * DD);
        for (int d = tid; d < DD; d += 256) neiS[n][d] = src[d];
    }
    __syncthreads();

    float p[NNEI + 1];
    #pragma unroll
    for (int n = 0; n <= NNEI; n++) p[n] = 0.f;
    for (int d = tid; d < DD; d += 256) {
        float a1 = Wal[d];
        float a2 = Wal[DD + d];
        p[NNEI] += a1 * curS[d];
        #pragma unroll
        for (int n = 0; n < NNEI; n++) p[n] += a2 * neiS[n][d];
    }
    #pragma unroll
    for (int n = 0; n <= NNEI; n++) {
        float s = warpsum(p[n]);
        if (lane == 0) atomicAdd(&red[n], s);
    }
    __syncthreads();

    float dtop = red[NNEI];
    float bb = bal[0];
    float sc[NNEI];
    float msk[NNEI];
    float mx = -1e30f;
    #pragma unroll
    for (int n = 0; n < NNEI; n++) {
        float a = lrelu(dtop + red[n] + bb);
        bool pad = (idxS[n] == LDIM - 1);
        msk[n] = pad ? 0.f : 1.f;
        a += pad ? NEGV : 0.f;
        sc[n] = a;
        mx = fmaxf(mx, a);
    }
    float sum = 0.f;
    float w[NNEI];
    #pragma unroll
    for (int n = 0; n < NNEI; n++) { w[n] = expf(sc[n] - mx); sum += w[n]; }
    float inv = 1.f / sum;
    float wt = 0.f;
    #pragma unroll
    for (int n = 0; n < NNEI; n++) { w[n] = w[n] * inv * msk[n]; wt += w[n]; }

    for (int d = tid; d < DD; d += 256) {
        float s = 0.f;
        #pragma unroll
        for (int n = 0; n < NNEI; n++) s += w[n] * neiS[n][d];
        wsum[(size_t)atom * DD + d] = s;
    }
    if (tid == 0) wtot[atom] = wt;
}

// ---------------- GRU combine ----------------
__global__ void gru_combine(const float* __restrict__ gi, const float* __restrict__ gh,
                            const float* __restrict__ h,
                            float* __restrict__ hOut, float* __restrict__ actOut, int Mrows)
{
    int i = blockIdx.x * blockDim.x + threadIdx.x;
    if (i >= Mrows * DD) return;
    int m = i / DD;
    int d = i - m * DD;
    const float* gim = gi + (size_t)m * D3;
    const float* ghm = gh + (size_t)m * D3;
    float r = sigm(gim[d] + ghm[d]);
    float z = sigm(gim[DD + d] + ghm[DD + d]);
    float n = tanhf(gim[2 * DD + d] + r * ghm[2 * DD + d]);
    float hv = h[i];
    float hn = (1.f - z) * n + z * hv;
    hOut[i] = hn;
    actOut[i] = hn > 0.f ? hn : 0.f;
}

// ---------------- mol prep: masked sum + per-atom s2 dot ----------------
__global__ void molprep_kernel(const float* __restrict__ cur, const float* __restrict__ amask,
                               const float* __restrict__ Wma,
                               float* __restrict__ mol, float* __restrict__ actmol,
                               float* __restrict__ s2)
{
    int b = blockIdx.x;
    int tid = threadIdx.x;
    for (int d = tid; d < DD; d += 256) {
        float s = 0.f;
        for (int l = 0; l < LDIM; l++)
            s += cur[((size_t)b * LDIM + l) * DD + d] * amask[b * LDIM + l];
        mol[b * DD + d] = s;
        actmol[b * DD + d] = s > 0.f ? s : 0.f;
    }
    int w = tid >> 5;
    int lane = tid & 31;
    for (int l = w; l < LDIM; l += 8) {
        float p = 0.f;
        const float* row = cur + ((size_t)b * LDIM + l) * DD;
        for (int d = lane; d < DD; d += 32) p += row[d] * Wma[DD + d];
        p = warpsum(p);
        if (lane == 0) s2[b * LDIM + l] = p;
    }
}

// ---------------- mol attention: weights + weighted atom sum ----------------
__global__ void molctx_kernel(const float* __restrict__ actmol,
                              const float* __restrict__ cur,
                              const float* __restrict__ s2,
                              const float* __restrict__ amask,
                              const float* __restrict__ Wma,
                              const float* __restrict__ bma,
                              float* __restrict__ mwsum,
                              float* __restrict__ mwtot)
{
    int b = blockIdx.x;
    int tid = threadIdx.x;
    int lane = tid & 31;
    __shared__ float redv;
    __shared__ float sc[LDIM];
    __shared__ float wS[LDIM];
    if (tid == 0) redv = 0.f;
    __syncthreads();

    float p = 0.f;
    for (int d = tid; d < DD; d += 256) p += actmol[b * DD + d] * Wma[d];
    p = warpsum(p);
    if (lane == 0) atomicAdd(&redv, p);
    __syncthreads();

    if (tid < LDIM) {
        float a = lrelu(redv + s2[b * LDIM + tid] + bma[0]);
        if (amask[b * LDIM + tid] == 0.f) a += NEGV;
        sc[tid] = a;
    }
    __syncthreads();

    float mx = -1e30f;
    for (int l = 0; l < LDIM; l++) mx = fmaxf(mx, sc[l]);
    float sum = 0.f;
    for (int l = 0; l < LDIM; l++) sum += expf(sc[l] - mx);
    float inv = 1.f / sum;
    if (tid < LDIM) wS[tid] = expf(sc[tid] - mx) * inv * amask[b * LDIM + tid];
    __syncthreads();

    for (int d = tid; d < DD; d += 256) {
        float s = 0.f;
        for (int l = 0; l < LDIM; l++)
            s += wS[l] * cur[((size_t)b * LDIM + l) * DD + d];
        mwsum[b * DD + d] = s;
    }
    if (tid == 0) {
        float wt = 0.f;
        for (int l = 0; l < LDIM; l++) wt += wS[l];
        mwtot[b] = wt;
    }
}

// ---------------- final projection ----------------
__global__ void final_kernel(const float* __restrict__ mol,
                             const float* __restrict__ Wm, const float* __restrict__ bm,
                             const float* __restrict__ Wo, const float* __restrict__ bo,
                             float* __restrict__ out)
{
    int b = blockIdx.x;
    int tid = threadIdx.x;
    int lane = tid & 31;
    __shared__ float featS[D2];
    __shared__ float ws[8];
    for (int j = tid; j < D2; j += 256)
        featS[j] = (j < DD) ? mol[b * DD + j] : (mol[b * DD + j - DD] + (float)(RR - 2));
    __syncthreads();
    float p = 0.f;
    for (int d = tid; d < DD; d += 256) {
        float s = bm[d];
        for (int j = 0; j < D2; j++) s += featS[j] * Wm[j * DD + d];
        p += s * Wo[d];
    }
    p = warpsum(p);
    if (lane == 0) ws[tid >> 5] = p;
    __syncthreads();
    if (tid == 0) {
        float t = 0.f;
        for (int i = 0; i < 8; i++) t += ws[i];
        out[b] = t + bo[0];
    }
}

// ---------------- host-side dispatch ----------------
static void tgemm(const float* A, int lda, int K,
                  const uint32_t* WTh, const uint32_t* WTl,
                  const float* bias, const float* rowscale, float* C,
                  int M, int Ntot, int act)
{
    dim3 g(M / 128, (Ntot + 63) / 64, 1);
    bfgemm_kernel<0><<<g, 256>>>(A, lda, K, WTh, WTl, bias, rowscale, C, M, Ntot, act,
                                 nullptr, nullptr, nullptr, nullptr, nullptr);
}

static void tgemm_dual(const float* A1, const uint32_t* W1h, const uint32_t* W1l,
                       const float* bias1, float* C1,
                       const float* A2, const uint32_t* W2h, const uint32_t* W2l,
                       const float* bias2, float* C2,
                       int M, int Ntot)
{
    dim3 g(M / 128, (Ntot + 63) / 64, 2);
    bfgemm_kernel<1><<<g, 256>>>(A1, DD, DD, W1h, W1l, bias1, nullptr, C1, M, Ntot, 0,
                                 A2, W2h, W2l, bias2, C2);
}

extern "C" void kernel_launch(void* const* d_in, const int* in_sizes, int n_in,
                              void* d_out, int out_size)
{
    const float* atom_list   = (const float*)d_in[0];
    const float* bond_list   = (const float*)d_in[1];
    const int*   adeg        = (const int*)d_in[2];
    const int*   bdeg        = (const int*)d_in[3];
    const float* amask       = (const float*)d_in[4];
    const float* W_atom      = (const float*)d_in[5];
    const float* b_atom      = (const float*)d_in[6];
    const float* W_nei       = (const float*)d_in[7];
    const float* b_nei       = (const float*)d_in[8];
    const float* W_align     = (const float*)d_in[9];
    const float* b_align     = (const float*)d_in[10];
    const float* W_attend    = (const float*)d_in[11];
    const float* b_attend    = (const float*)d_in[12];
    const float* Wih         = (const float*)d_in[13];
    const float* Whh         = (const float*)d_in[14];
    const float* bih         = (const float*)d_in[15];
    const float* bhh         = (const float*)d_in[16];
    const float* W_mol_align = (const float*)d_in[17];
    const float* b_mol_align = (const float*)d_in[18];
    const float* W_mol_att   = (const float*)d_in[19];
    const float* b_mol_att   = (const float*)d_in[20];
    const float* mWih        = (const float*)d_in[21];
    const float* mWhh        = (const float*)d_in[22];
    const float* mbih        = (const float*)d_in[23];
    const float* mbhh        = (const float*)d_in[24];
    const float* W_metric    = (const float*)d_in[25];
    const float* b_metric    = (const float*)d_in[26];
    const float* W_out       = (const float*)d_in[27];
    const float* b_out       = (const float*)d_in[28];

    float *atomfeat, *atompad, *cur, *ctx, *wsum, *wtot, *concat, *nei0, *gi, *gh;
    float *s2, *mol, *actmol, *mwsum, *mwtot, *mctx, *mgi, *mgh;
    uint32_t *WT_atom_h, *WT_atom_l, *WT_nei_h, *WT_nei_l, *WT_att_h, *WT_att_l;
    uint32_t *WT_molatt_h, *WT_molatt_l, *Wih_h, *Wih_l, *Whh_h, *Whh_l;
    uint32_t *mWih_h, *mWih_l, *mWhh_h, *mWhh_l;
    cudaGetSymbolAddress((void**)&atomfeat, g_atomfeat);
    cudaGetSymbolAddress((void**)&atompad, g_atompad);
    cudaGetSymbolAddress((void**)&cur, g_cur);
    cudaGetSymbolAddress((void**)&ctx, g_ctx);
    cudaGetSymbolAddress((void**)&wsum, g_wsum);
    cudaGetSymbolAddress((void**)&wtot, g_wtot);
    cudaGetSymbolAddress((void**)&concat, g_concat);
    cudaGetSymbolAddress((void**)&nei0, g_nei0);
    cudaGetSymbolAddress((void**)&gi, g_gi);
    cudaGetSymbolAddress((void**)&gh, g_gh);
    cudaGetSymbolAddress((void**)&s2, g_s2);
    cudaGetSymbolAddress((void**)&mol, g_mol);
    cudaGetSymbolAddress((void**)&actmol, g_actmol);
    cudaGetSymbolAddress((void**)&mwsum, g_mwsum);
    cudaGetSymbolAddress((void**)&mwtot, g_mwtot);
    cudaGetSymbolAddress((void**)&mctx, g_mctx);
    cudaGetSymbolAddress((void**)&mgi, g_mgi);
    cudaGetSymbolAddress((void**)&mgh, g_mgh);
    cudaGetSymbolAddress((void**)&WT_atom_h, g_WT_atom_h);
    cudaGetSymbolAddress((void**)&WT_atom_l, g_WT_atom_l);
    cudaGetSymbolAddress((void**)&WT_nei_h, g_WT_nei_h);
    cudaGetSymbolAddress((void**)&WT_nei_l, g_WT_nei_l);
    cudaGetSymbolAddress((void**)&WT_att_h, g_WT_att_h);
    cudaGetSymbolAddress((void**)&WT_att_l, g_WT_att_l);
    cudaGetSymbolAddress((void**)&WT_molatt_h, g_WT_molatt_h);
    cudaGetSymbolAddress((void**)&WT_molatt_l, g_WT_molatt_l);
    cudaGetSymbolAddress((void**)&Wih_h, g_Wih_h);
    cudaGetSymbolAddress((void**)&Wih_l, g_Wih_l);
    cudaGetSymbolAddress((void**)&Whh_h, g_Whh_h);
    cudaGetSymbolAddress((void**)&Whh_l, g_Whh_l);
    cudaGetSymbolAddress((void**)&mWih_h, g_mWih_h);
    cudaGetSymbolAddress((void**)&mWih_l, g_mWih_l);
    cudaGetSymbolAddress((void**)&mWhh_h, g_mWhh_h);
    cudaGetSymbolAddress((void**)&mWhh_l, g_mWhh_l);

    float* h = atomfeat;   // h aliases atomfeat; updated in place by gru_combine

    // 0) weight prep
    {
        int n;
        n = 1800 * KPW; prep_pad_bf<<<(n + 255) / 256, 256>>>(Wih, Wih_h, Wih_l, 1800, DD);
        n = 1800 * KPW; prep_pad_bf<<<(n + 255) / 256, 256>>>(Whh, Whh_h, Whh_l, 1800, DD);
        n = 600 * KPW;  prep_pad_bf<<<(n + 255) / 256, 256>>>(mWih, mWih_h, mWih_l, 600, DD);
        n = 600 * KPW;  prep_pad_bf<<<(n + 255) / 256, 256>>>(mWhh, mWhh_h, mWhh_l, 600, DD);
        n = 200 * KPW;  prep_trans_bf<<<(n + 255) / 256, 256>>>(W_atom, WT_atom_h, WT_atom_l, 1, FAA, DD);
        n = 200 * KPW;  prep_trans_bf<<<(n + 255) / 256, 256>>>(W_nei, WT_nei_h, WT_nei_l, 1, FC, DD);
        n = 3 * 200 * KPW; prep_trans_bf<<<(n + 255) / 256, 256>>>(W_attend, WT_att_h, WT_att_l, 3, DD, DD);
        n = 200 * KPW;  prep_trans_bf<<<(n + 255) / 256, 256>>>(W_mol_att, WT_molatt_h, WT_molatt_l, 1, DD, DD);
    }

    // 1) atom_feature = lrelu(atom_list @ W_atom + b_atom)
    pad_atom_kernel<<<(NATOM * KPAD + 255) / 256, 256>>>(atom_list, atompad);
    tgemm(atompad, KPAD, KPAD, WT_atom_h, WT_atom_l, b_atom, nullptr, atomfeat, NATOM, DD, 1);

    // 2) nei0 = lrelu(concat @ W_nei + b_nei)
    build_concat<<<(NROWN * KPAD + 255) / 256, 256>>>(atom_list, bond_list, adeg, bdeg, concat);
    tgemm(concat, KPAD, KPAD, WT_nei_h, WT_nei_l, b_nei, nullptr, nei0, NROWN, DD, 1);

    // 3) atom GRU rounds
    for (int r = 0; r < RR; r++) {
        const float* curp = (r == 0) ? atomfeat : cur;
        ctx_kernel<<<NATOM, 256>>>(curp, (r == 0) ? nei0 : nullptr, adeg,
                                   W_align + (size_t)r * D2, b_align + r,
                                   wsum, wtot, (r == 0) ? 1 : 0);
        tgemm(wsum, DD, DD, WT_att_h + (size_t)r * 200 * KPW, WT_att_l + (size_t)r * 200 * KPW,
              b_attend + r * DD, wtot, ctx, NATOM, DD, 2);
        tgemm_dual(ctx, Wih_h + (size_t)r * D3 * KPW, Wih_l + (size_t)r * D3 * KPW,
                   bih + r * D3, gi,
                   h, Whh_h + (size_t)r * D3 * KPW, Whh_l + (size_t)r * D3 * KPW,
                   bhh + r * D3, gh, NATOM, D3);
        gru_combine<<<(NATOM * DD + 255) / 256, 256>>>(gi, gh, h, h, cur, NATOM);
    }

    // 4) mol phase
    molprep_kernel<<<BDIM, 256>>>(cur, amask, W_mol_align, mol, actmol, s2);
    for (int t = 0; t < TTI; t++) {
        molctx_kernel<<<BDIM, 256>>>(actmol, cur, s2, amask, W_mol_align, b_mol_align,
                                     mwsum, mwtot);
        tgemm(mwsum, DD, DD, WT_molatt_h, WT_molatt_l, b_mol_att, mwtot, mctx, BDIM, DD, 2);
        tgemm_dual(mctx, mWih_h, mWih_l, mbih, mgi,
                   mol, mWhh_h, mWhh_l, mbhh, mgh, BDIM, D3);
        gru_combine<<<(BDIM * DD + 255) / 256, 256>>>(mgi, mgh, mol, mol, actmol, BDIM);
    }

    // 5) final projection
    final_kernel<<<BDIM, 256>>>(mol, W_metric, b_metric, W_out, b_out, (float*)d_out);
}

// round 14
// speedup vs baseline: 1.4114x; 1.1962x over previous
#include <cuda_runtime.h>
#include <cuda_bf16.h>
#include <math.h>
#include <stdint.h>

typedef unsigned long long u64;

#define BDIM 128
#define LDIM 128
#define NNEI 6
#define FAA 39
#define FBB 10
#define FC 49
#define DD 200
#define D2 400
#define D3 600
#define RR 3
#define TTI 2
#define MBOND 256
#define NEGV -9e8f
#define NATOM (BDIM*LDIM)    /* 16384 */
#define NROWN (NATOM*NNEI)   /* 98304 */
#define KPAD 64
#define KP 224               /* padded K for weight buffers */
#define KPW (KP/2)           /* packed pairs per row = 112 */

// ---------------- device scratch (static, no allocation) ----------------
__device__ float g_atomfeat[NATOM*DD];   // also serves as h (updated in place)
__device__ float g_atompad[NATOM*KPAD];
__device__ float g_cur[NATOM*DD];
__device__ float g_ctx[NATOM*DD];
__device__ float g_wsum[NATOM*DD];
__device__ float g_wtot[NATOM];
__device__ float g_concat[NROWN*KPAD];
__device__ float g_nei0[NROWN*DD];
__device__ float g_gi[NATOM*D3];
__device__ float g_gh[NATOM*D3];
__device__ float g_s2[NATOM];
__device__ float g_mol[BDIM*DD];
__device__ float g_actmol[BDIM*DD];
__device__ float g_mwsum[BDIM*DD];
__device__ float g_mwtot[BDIM];
__device__ float g_mctx[BDIM*DD];
__device__ float g_mgi[BDIM*D3];
__device__ float g_mgh[BDIM*D3];
// packed bf16-pair weights (hi and lo planes)
__device__ uint32_t g_WT_atom_h[200*KPW],  g_WT_atom_l[200*KPW];
__device__ uint32_t g_WT_nei_h[200*KPW],   g_WT_nei_l[200*KPW];
__device__ uint32_t g_WT_att_h[3*200*KPW], g_WT_att_l[3*200*KPW];
__device__ uint32_t g_WT_molatt_h[200*KPW],g_WT_molatt_l[200*KPW];
__device__ uint32_t g_Wih_h[3*600*KPW],    g_Wih_l[3*600*KPW];
__device__ uint32_t g_Whh_h[3*600*KPW],    g_Whh_l[3*600*KPW];
__device__ uint32_t g_mWih_h[600*KPW],     g_mWih_l[600*KPW];
__device__ uint32_t g_mWhh_h[600*KPW],     g_mWhh_l[600*KPW];

// ---------------- helpers ----------------
__device__ __forceinline__ float warpsum(float v) {
    #pragma unroll
    for (int o = 16; o > 0; o >>= 1) v += __shfl_down_sync(0xffffffffu, v, o);
    return v;
}
__device__ __forceinline__ float warpall(float v) {
    #pragma unroll
    for (int o = 16; o > 0; o >>= 1) v += __shfl_xor_sync(0xffffffffu, v, o);
    return v;
}
__device__ __forceinline__ float lrelu(float x) { return x > 0.f ? x : 0.01f * x; }
__device__ __forceinline__ float eluf(float x)  { return x > 0.f ? x : expm1f(x); }
__device__ __forceinline__ float sigm(float x)  { return 1.f / (1.f + expf(-x)); }

__device__ __forceinline__ void split_bf16(float x, __nv_bfloat16& h, __nv_bfloat16& l) {
    h = __float2bfloat16_rn(x);
    l = __float2bfloat16_rn(x - __bfloat162float(h));
}
__device__ __forceinline__ uint32_t pack2(__nv_bfloat16 a, __nv_bfloat16 b) {
    __nv_bfloat162 p = __halves2bfloat162(a, b);
    return *reinterpret_cast<uint32_t*>(&p);
}

#define MMAB(c, a, b) \
    asm volatile("mma.sync.aligned.m16n8k16.row.col.f32.bf16.bf16.f32 " \
        "{%0,%1,%2,%3}, {%4,%5,%6,%7}, {%8,%9}, {%0,%1,%2,%3};" \
        : "+f"((c)[0]), "+f"((c)[1]), "+f"((c)[2]), "+f"((c)[3]) \
        : "r"((a)[0]), "r"((a)[1]), "r"((a)[2]), "r"((a)[3]), \
          "r"((b)[0]), "r"((b)[1]))

// =====================================================================
// Split-bf16 tensor GEMM, BM=128 BN=128, register prefetch.
// C[M,Ntot] = act(A[M,K](lda) @ WT^T + rs[m]*bias)
// DUAL=1: blockIdx.z selects (A2, W2, bias2, C2) for a second GEMM.
// 8 warps = 4m x 2n; warp tile 32x64 (2 mtiles x 8 ntiles).
// =====================================================================
template<int DUAL>
__global__ __launch_bounds__(256) void bfgemm_kernel(
    const float* __restrict__ A, int lda, int K,
    const uint32_t* __restrict__ WTh, const uint32_t* __restrict__ WTl,
    const float* __restrict__ bias,
    const float* __restrict__ rowscale,
    float* __restrict__ C, int M, int Ntot, int act,
    const float* A2, const uint32_t* W2h, const uint32_t* W2l,
    const float* bias2, float* C2)
{
    if (DUAL && blockIdx.z == 1) {
        A = A2; WTh = W2h; WTl = W2l; bias = bias2; C = C2;
    }

    __shared__ uint32_t APh[8][132], APl[8][132];
    __shared__ uint32_t BPh[8][136], BPl[8][136];

    const int tid = threadIdx.x;
    const int wid = tid >> 5;
    const int lane = tid & 31;
    const int gid = lane >> 2;
    const int tg = lane & 3;
    const int bm0 = blockIdx.x * 128;
    const int bn0 = blockIdx.y * 128;
    const int wm = (wid & 3) * 32;
    const int wn = (wid >> 2) * 64;

    // A loader (2 float4/thread), B loader (1 uint4 per plane/thread)
    const int a_r0 = tid >> 2, a_c4 = (tid & 3) << 2;
    const int b_r = tid >> 1, b_kp4 = (tid & 1) << 2;

    float c[2][8][4];
    #pragma unroll
    for (int mt = 0; mt < 2; mt++)
        #pragma unroll
        for (int nt = 0; nt < 8; nt++)
            #pragma unroll
            for (int q = 0; q < 4; q++) c[mt][nt][q] = 0.f;

    const int nch = (K + 15) >> 4;

    float4 av[2];
    uint4 bvh, bvl;
    {
        #pragma unroll
        for (int it = 0; it < 2; it++) {
            int r = a_r0 + it * 64;
            av[it] = (a_c4 < K) ? *reinterpret_cast<const float4*>(A + (size_t)(bm0 + r) * lda + a_c4)
                                : make_float4(0.f, 0.f, 0.f, 0.f);
        }
        int n = bn0 + b_r;
        if (n < Ntot) {
            size_t off = (size_t)n * KPW + b_kp4;
            bvh = *reinterpret_cast<const uint4*>(WTh + off);
            bvl = *reinterpret_cast<const uint4*>(WTl + off);
        } else { bvh = make_uint4(0u,0u,0u,0u); bvl = make_uint4(0u,0u,0u,0u); }
    }

    for (int chn = 0; chn < nch; chn++) {
        #pragma unroll
        for (int it = 0; it < 2; it++) {
            int r = a_r0 + it * 64;
            int kp = a_c4 >> 1;
            __nv_bfloat16 h0, l0, h1, l1, h2, l2, h3, l3;
            split_bf16(av[it].x, h0, l0); split_bf16(av[it].y, h1, l1);
            split_bf16(av[it].z, h2, l2); split_bf16(av[it].w, h3, l3);
            APh[kp][r]     = pack2(h0, h1);
            APh[kp + 1][r] = pack2(h2, h3);
            APl[kp][r]     = pack2(l0, l1);
            APl[kp + 1][r] = pack2(l2, l3);
        }
        BPh[b_kp4 + 0][b_r] = bvh.x; BPh[b_kp4 + 1][b_r] = bvh.y;
        BPh[b_kp4 + 2][b_r] = bvh.z; BPh[b_kp4 + 3][b_r] = bvh.w;
        BPl[b_kp4 + 0][b_r] = bvl.x; BPl[b_kp4 + 1][b_r] = bvl.y;
        BPl[b_kp4 + 2][b_r] = bvl.z; BPl[b_kp4 + 3][b_r] = bvl.w;
        __syncthreads();

        if (chn + 1 < nch) {
            const int k0 = (chn + 1) << 4;
            #pragma unroll
            for (int it = 0; it < 2; it++) {
                int r = a_r0 + it * 64;
                int k = k0 + a_c4;
                av[it] = (k < K) ? *reinterpret_cast<const float4*>(A + (size_t)(bm0 + r) * lda + k)
                                 : make_float4(0.f, 0.f, 0.f, 0.f);
            }
            int n = bn0 + b_r;
            if (n < Ntot) {
                size_t off = (size_t)n * KPW + (k0 >> 1) + b_kp4;
                bvh = *reinterpret_cast<const uint4*>(WTh + off);
                bvl = *reinterpret_cast<const uint4*>(WTl + off);
            } else { bvh = make_uint4(0u,0u,0u,0u); bvl = make_uint4(0u,0u,0u,0u); }
        }

        uint32_t ah[2][4], al[2][4];
        #pragma unroll
        for (int mt = 0; mt < 2; mt++) {
            int mr = wm + mt * 16;
            ah[mt][0] = APh[tg][mr + gid];
            ah[mt][1] = APh[tg][mr + gid + 8];
            ah[mt][2] = APh[tg + 4][mr + gid];
            ah[mt][3] = APh[tg + 4][mr + gid + 8];
            al[mt][0] = APl[tg][mr + gid];
            al[mt][1] = APl[tg][mr + gid + 8];
            al[mt][2] = APl[tg + 4][mr + gid];
            al[mt][3] = APl[tg + 4][mr + gid + 8];
        }
        #pragma unroll
        for (int nt = 0; nt < 8; nt++) {
            int nc = wn + nt * 8 + gid;
            uint32_t bh[2] = { BPh[tg][nc], BPh[tg + 4][nc] };
            uint32_t bl[2] = { BPl[tg][nc], BPl[tg + 4][nc] };
            #pragma unroll
            for (int mt = 0; mt < 2; mt++) {
                MMAB(c[mt][nt], ah[mt], bh);
                MMAB(c[mt][nt], ah[mt], bl);
                MMAB(c[mt][nt], al[mt], bh);
            }
        }
        __syncthreads();
    }

    #pragma unroll
    for (int mt = 0; mt < 2; mt++) {
        #pragma unroll
        for (int half = 0; half < 2; half++) {
            int m = bm0 + wm + mt * 16 + gid + half * 8;
            float rs = rowscale ? rowscale[m] : 1.f;
            float* crow = C + (size_t)m * Ntot;
            #pragma unroll
            for (int nt = 0; nt < 8; nt++) {
                int n = bn0 + wn + nt * 8 + 2 * tg;
                float v0 = c[mt][nt][half * 2 + 0];
                float v1 = c[mt][nt][half * 2 + 1];
                if (n < Ntot) {
                    float v = v0 + rs * (bias ? bias[n] : 0.f);
                    if (act == 1) v = lrelu(v);
                    else if (act == 2) v = eluf(v);
                    crow[n] = v;
                }
                if (n + 1 < Ntot) {
                    float v = v1 + rs * (bias ? bias[n + 1] : 0.f);
                    if (act == 1) v = lrelu(v);
                    else if (act == 2) v = eluf(v);
                    crow[n + 1] = v;
                }
            }
        }
    }
}

// ---------------- weight prep: [NT,K] row-major -> packed hi/lo [NT,KPW] ----------------
__global__ void prep_pad_bf(const float* __restrict__ in,
                            uint32_t* __restrict__ outh, uint32_t* __restrict__ outl,
                            int NT, int K)
{
    int i = blockIdx.x * 256 + threadIdx.x;
    if (i >= NT * KPW) return;
    int n = i / KPW, kp = i - n * KPW;
    int k = kp << 1;
    float x0 = (k < K) ? in[(size_t)n * K + k] : 0.f;
    float x1 = (k + 1 < K) ? in[(size_t)n * K + k + 1] : 0.f;
    __nv_bfloat16 h0, l0, h1, l1;
    split_bf16(x0, h0, l0); split_bf16(x1, h1, l1);
    outh[i] = pack2(h0, h1);
    outl[i] = pack2(l0, l1);
}

// ---------------- weight prep: [R,K,N] -> packed hi/lo [R,N,KPW] ----------------
__global__ void prep_trans_bf(const float* __restrict__ in,
                              uint32_t* __restrict__ outh, uint32_t* __restrict__ outl,
                              int R, int K, int N)
{
    int i = blockIdx.x * 256 + threadIdx.x;
    if (i >= R * N * KPW) return;
    int kp = i % KPW;
    int rn = i / KPW;
    int n = rn % N;
    int r = rn / N;
    int k = kp << 1;
    float x0 = (k < K) ? in[((size_t)r * K + k) * N + n] : 0.f;
    float x1 = (k + 1 < K) ? in[((size_t)r * K + k + 1) * N + n] : 0.f;
    __nv_bfloat16 h0, l0, h1, l1;
    split_bf16(x0, h0, l0); split_bf16(x1, h1, l1);
    outh[i] = pack2(h0, h1);
    outl[i] = pack2(l0, l1);
}

// ---------------- pad atom_list [NATOM,39] -> [NATOM,64] ----------------
__global__ void pad_atom_kernel(const float* __restrict__ atom_list, float* __restrict__ out)
{
    int i = blockIdx.x * blockDim.x + threadIdx.x;
    if (i >= NATOM * KPAD) return;
    int row = i >> 6;
    int f = i & 63;
    out[i] = (f < FAA) ? atom_list[row * FAA + f] : 0.f;
}

// ---------------- build concat(atom_nei, bond_nei) [NROWN, 64] padded ----------------
__global__ void build_concat(const float* __restrict__ atom_list,
                             const float* __restrict__ bond_list,
                             const int* __restrict__ adeg,
                             const int* __restrict__ bdeg,
                             float* __restrict__ out)
{
    int i = blockIdx.x * blockDim.x + threadIdx.x;
    if (i >= NROWN * KPAD) return;
    int row = i >> 6;
    int f = i & 63;
    int b = row / (LDIM * NNEI);
    float v = 0.f;
    if (f < FAA) {
        int a = adeg[row];
        v = atom_list[((size_t)b * LDIM + a) * FAA + f];
    } else if (f < FC) {
        int bd = bdeg[row];
        v = bond_list[((size_t)b * MBOND + bd) * FBB + (f - FAA)];
    }
    out[i] = v;
}

// ---------------- attention: warp-per-atom softmax + weighted neighbor sum ----------------
// 256 threads = 8 warps; atom = blockIdx.x*8 + wid. All warp-local (shuffles).
#define CHK 7   /* ceil(200/32) */
__global__ void ctx_kernel(const float* __restrict__ cur,
                           const float* __restrict__ neiBuf,
                           const int* __restrict__ adeg,
                           const float* __restrict__ Wal,
                           const float* __restrict__ bal,
                           float* __restrict__ wsum,
                           float* __restrict__ wtot,
                           int firstRound)
{
    const int tid = threadIdx.x;
    const int wid = tid >> 5;
    const int lane = tid & 31;
    const int atom = blockIdx.x * 8 + wid;
    const int b = atom / LDIM;

    // neighbor indices (lane n holds idx n; broadcast to all lanes)
    int myidx = (lane < NNEI) ? adeg[atom * NNEI + lane] : 0;
    int idx[NNEI];
    #pragma unroll
    for (int n = 0; n < NNEI; n++) idx[n] = __shfl_sync(0xffffffffu, myidx, n);

    const float* neirow[NNEI];
    #pragma unroll
    for (int n = 0; n < NNEI; n++)
        neirow[n] = firstRound ? (neiBuf + ((size_t)atom * NNEI + n) * DD)
                               : (cur + ((size_t)(b * LDIM + idx[n])) * DD);
    const float* currow = cur + (size_t)atom * DD;

    float curv[CHK], neiv[NNEI][CHK], w1[CHK], w2[CHK];
    #pragma unroll
    for (int i = 0; i < CHK; i++) {
        int d = lane + 32 * i;
        bool ok = d < DD;
        curv[i] = ok ? currow[d] : 0.f;
        w1[i] = ok ? Wal[d] : 0.f;
        w2[i] = ok ? Wal[DD + d] : 0.f;
        #pragma unroll
        for (int n = 0; n < NNEI; n++) neiv[n][i] = ok ? neirow[n][d] : 0.f;
    }

    // dots
    float pc = 0.f;
    #pragma unroll
    for (int i = 0; i < CHK; i++) pc += w1[i] * curv[i];
    pc = warpall(pc);
    float pn[NNEI];
    #pragma unroll
    for (int n = 0; n < NNEI; n++) {
        float p = 0.f;
        #pragma unroll
        for (int i = 0; i < CHK; i++) p += w2[i] * neiv[n][i];
        pn[n] = warpall(p);
    }

    // softmax over neighbors (redundant per lane)
    float bb = bal[0];
    float sc[NNEI], msk[NNEI];
    float mx = -1e30f;
    #pragma unroll
    for (int n = 0; n < NNEI; n++) {
        float a = lrelu(pc + pn[n] + bb);
        bool pad = (idx[n] == LDIM - 1);
        msk[n] = pad ? 0.f : 1.f;
        a += pad ? NEGV : 0.f;
        sc[n] = a;
        mx = fmaxf(mx, a);
    }
    float sum = 0.f;
    float w[NNEI];
    #pragma unroll
    for (int n = 0; n < NNEI; n++) { w[n] = expf(sc[n] - mx); sum += w[n]; }
    float inv = 1.f / sum;
    float wt = 0.f;
    #pragma unroll
    for (int n = 0; n < NNEI; n++) { w[n] = w[n] * inv * msk[n]; wt += w[n]; }

    float* outrow = wsum + (size_t)atom * DD;
    #pragma unroll
    for (int i = 0; i < CHK; i++) {
        int d = lane + 32 * i;
        if (d < DD) {
            float s = 0.f;
            #pragma unroll
            for (int n = 0; n < NNEI; n++) s += w[n] * neiv[n][i];
            outrow[d] = s;
        }
    }
    if (lane == 0) wtot[atom] = wt;
}

// ---------------- GRU combine ----------------
__global__ void gru_combine(const float* __restrict__ gi, const float* __restrict__ gh,
                            const float* __restrict__ h,
                            float* __restrict__ hOut, float* __restrict__ actOut, int Mrows)
{
    int i = blockIdx.x * blockDim.x + threadIdx.x;
    if (i >= Mrows * DD) return;
    int m = i / DD;
    int d = i - m * DD;
    const float* gim = gi + (size_t)m * D3;
    const float* ghm = gh + (size_t)m * D3;
    float r = sigm(gim[d] + ghm[d]);
    float z = sigm(gim[DD + d] + ghm[DD + d]);
    float n = tanhf(gim[2 * DD + d] + r * ghm[2 * DD + d]);
    float hv = h[i];
    float hn = (1.f - z) * n + z * hv;
    hOut[i] = hn;
    actOut[i] = hn > 0.f ? hn : 0.f;
}

// ---------------- mol prep: masked sum + per-atom s2 dot ----------------
__global__ void molprep_kernel(const float* __restrict__ cur, const float* __restrict__ amask,
                               const float* __restrict__ Wma,
                               float* __restrict__ mol, float* __restrict__ actmol,
                               float* __restrict__ s2)
{
    int b = blockIdx.x;
    int tid = threadIdx.x;
    for (int d = tid; d < DD; d += 256) {
        float s = 0.f;
        for (int l = 0; l < LDIM; l++)
            s += cur[((size_t)b * LDIM + l) * DD + d] * amask[b * LDIM + l];
        mol[b * DD + d] = s;
        actmol[b * DD + d] = s > 0.f ? s : 0.f;
    }
    int w = tid >> 5;
    int lane = tid & 31;
    for (int l = w; l < LDIM; l += 8) {
        float p = 0.f;
        const float* row = cur + ((size_t)b * LDIM + l) * DD;
        for (int d = lane; d < DD; d += 32) p += row[d] * Wma[DD + d];
        p = warpsum(p);
        if (lane == 0) s2[b * LDIM + l] = p;
    }
}

// ---------------- mol attention: weights + weighted atom sum ----------------
__global__ void molctx_kernel(const float* __restrict__ actmol,
                              const float* __restrict__ cur,
                              const float* __restrict__ s2,
                              const float* __restrict__ amask,
                              const float* __restrict__ Wma,
                              const float* __restrict__ bma,
                              float* __restrict__ mwsum,
                              float* __restrict__ mwtot)
{
    int b = blockIdx.x;
    int tid = threadIdx.x;
    int lane = tid & 31;
    __shared__ float redv;
    __shared__ float sc[LDIM];
    __shared__ float wS[LDIM];
    if (tid == 0) redv = 0.f;
    __syncthreads();

    float p = 0.f;
    for (int d = tid; d < DD; d += 256) p += actmol[b * DD + d] * Wma[d];
    p = warpsum(p);
    if (lane == 0) atomicAdd(&redv, p);
    __syncthreads();

    if (tid < LDIM) {
        float a = lrelu(redv + s2[b * LDIM + tid] + bma[0]);
        if (amask[b * LDIM + tid] == 0.f) a += NEGV;
        sc[tid] = a;
    }
    __syncthreads();

    float mx = -1e30f;
    for (int l = 0; l < LDIM; l++) mx = fmaxf(mx, sc[l]);
    float sum = 0.f;
    for (int l = 0; l < LDIM; l++) sum += expf(sc[l] - mx);
    float inv = 1.f / sum;
    if (tid < LDIM) wS[tid] = expf(sc[tid] - mx) * inv * amask[b * LDIM + tid];
    __syncthreads();

    for (int d = tid; d < DD; d += 256) {
        float s = 0.f;
        for (int l = 0; l < LDIM; l++)
            s += wS[l] * cur[((size_t)b * LDIM + l) * DD + d];
        mwsum[b * DD + d] = s;
    }
    if (tid == 0) {
        float wt = 0.f;
        for (int l = 0; l < LDIM; l++) wt += wS[l];
        mwtot[b] = wt;
    }
}

// ---------------- final projection ----------------
__global__ void final_kernel(const float* __restrict__ mol,
                             const float* __restrict__ Wm, const float* __restrict__ bm,
                             const float* __restrict__ Wo, const float* __restrict__ bo,
                             float* __restrict__ out)
{
    int b = blockIdx.x;
    int tid = threadIdx.x;
    int lane = tid & 31;
    __shared__ float featS[D2];
    __shared__ float ws[8];
    for (int j = tid; j < D2; j += 256)
        featS[j] = (j < DD) ? mol[b * DD + j] : (mol[b * DD + j - DD] + (float)(RR - 2));
    __syncthreads();
    float p = 0.f;
    for (int d = tid; d < DD; d += 256) {
        float s = bm[d];
        for (int j = 0; j < D2; j++) s += featS[j] * Wm[j * DD + d];
        p += s * Wo[d];
    }
    p = warpsum(p);
    if (lane == 0) ws[tid >> 5] = p;
    __syncthreads();
    if (tid == 0) {
        float t = 0.f;
        for (int i = 0; i < 8; i++) t += ws[i];
        out[b] = t + bo[0];
    }
}

// ---------------- host-side dispatch ----------------
static void tgemm(const float* A, int lda, int K,
                  const uint32_t* WTh, const uint32_t* WTl,
                  const float* bias, const float* rowscale, float* C,
                  int M, int Ntot, int act)
{
    dim3 g(M / 128, (Ntot + 127) / 128, 1);
    bfgemm_kernel<0><<<g, 256>>>(A, lda, K, WTh, WTl, bias, rowscale, C, M, Ntot, act,
                                 nullptr, nullptr, nullptr, nullptr, nullptr);
}

static void tgemm_dual(const float* A1, const uint32_t* W1h, const uint32_t* W1l,
                       const float* bias1, float* C1,
                       const float* A2, const uint32_t* W2h, const uint32_t* W2l,
                       const float* bias2, float* C2,
                       int M, int Ntot)
{
    dim3 g(M / 128, (Ntot + 127) / 128, 2);
    bfgemm_kernel<1><<<g, 256>>>(A1, DD, DD, W1h, W1l, bias1, nullptr, C1, M, Ntot, 0,
                                 A2, W2h, W2l, bias2, C2);
}

extern "C" void kernel_launch(void* const* d_in, const int* in_sizes, int n_in,
                              void* d_out, int out_size)
{
    const float* atom_list   = (const float*)d_in[0];
    const float* bond_list   = (const float*)d_in[1];
    const int*   adeg        = (const int*)d_in[2];
    const int*   bdeg        = (const int*)d_in[3];
    const float* amask       = (const float*)d_in[4];
    const float* W_atom      = (const float*)d_in[5];
    const float* b_atom      = (const float*)d_in[6];
    const float* W_nei       = (const float*)d_in[7];
    const float* b_nei       = (const float*)d_in[8];
    const float* W_align     = (const float*)d_in[9];
    const float* b_align     = (const float*)d_in[10];
    const float* W_attend    = (const float*)d_in[11];
    const float* b_attend    = (const float*)d_in[12];
    const float* Wih         = (const float*)d_in[13];
    const float* Whh         = (const float*)d_in[14];
    const float* bih         = (const float*)d_in[15];
    const float* bhh         = (const float*)d_in[16];
    const float* W_mol_align = (const float*)d_in[17];
    const float* b_mol_align = (const float*)d_in[18];
    const float* W_mol_att   = (const float*)d_in[19];
    const float* b_mol_att   = (const float*)d_in[20];
    const float* mWih        = (const float*)d_in[21];
    const float* mWhh        = (const float*)d_in[22];
    const float* mbih        = (const float*)d_in[23];
    const float* mbhh        = (const float*)d_in[24];
    const float* W_metric    = (const float*)d_in[25];
    const float* b_metric    = (const float*)d_in[26];
    const float* W_out       = (const float*)d_in[27];
    const float* b_out       = (const float*)d_in[28];

    float *atomfeat, *atompad, *cur, *ctx, *wsum, *wtot, *concat, *nei0, *gi, *gh;
    float *s2, *mol, *actmol, *mwsum, *mwtot, *mctx, *mgi, *mgh;
    uint32_t *WT_atom_h, *WT_atom_l, *WT_nei_h, *WT_nei_l, *WT_att_h, *WT_att_l;
    uint32_t *WT_molatt_h, *WT_molatt_l, *Wih_h, *Wih_l, *Whh_h, *Whh_l;
    uint32_t *mWih_h, *mWih_l, *mWhh_h, *mWhh_l;
    cudaGetSymbolAddress((void**)&atomfeat, g_atomfeat);
    cudaGetSymbolAddress((void**)&atompad, g_atompad);
    cudaGetSymbolAddress((void**)&cur, g_cur);
    cudaGetSymbolAddress((void**)&ctx, g_ctx);
    cudaGetSymbolAddress((void**)&wsum, g_wsum);
    cudaGetSymbolAddress((void**)&wtot, g_wtot);
    cudaGetSymbolAddress((void**)&concat, g_concat);
    cudaGetSymbolAddress((void**)&nei0, g_nei0);
    cudaGetSymbolAddress((void**)&gi, g_gi);
    cudaGetSymbolAddress((void**)&gh, g_gh);
    cudaGetSymbolAddress((void**)&s2, g_s2);
    cudaGetSymbolAddress((void**)&mol, g_mol);
    cudaGetSymbolAddress((void**)&actmol, g_actmol);
    cudaGetSymbolAddress((void**)&mwsum, g_mwsum);
    cudaGetSymbolAddress((void**)&mwtot, g_mwtot);
    cudaGetSymbolAddress((void**)&mctx, g_mctx);
    cudaGetSymbolAddress((void**)&mgi, g_mgi);
    cudaGetSymbolAddress((void**)&mgh, g_mgh);
    cudaGetSymbolAddress((void**)&WT_atom_h, g_WT_atom_h);
    cudaGetSymbolAddress((void**)&WT_atom_l, g_WT_atom_l);
    cudaGetSymbolAddress((void**)&WT_nei_h, g_WT_nei_h);
    cudaGetSymbolAddress((void**)&WT_nei_l, g_WT_nei_l);
    cudaGetSymbolAddress((void**)&WT_att_h, g_WT_att_h);
    cudaGetSymbolAddress((void**)&WT_att_l, g_WT_att_l);
    cudaGetSymbolAddress((void**)&WT_molatt_h, g_WT_molatt_h);
    cudaGetSymbolAddress((void**)&WT_molatt_l, g_WT_molatt_l);
    cudaGetSymbolAddress((void**)&Wih_h, g_Wih_h);
    cudaGetSymbolAddress((void**)&Wih_l, g_Wih_l);
    cudaGetSymbolAddress((void**)&Whh_h, g_Whh_h);
    cudaGetSymbolAddress((void**)&Whh_l, g_Whh_l);
    cudaGetSymbolAddress((void**)&mWih_h, g_mWih_h);
    cudaGetSymbolAddress((void**)&mWih_l, g_mWih_l);
    cudaGetSymbolAddress((void**)&mWhh_h, g_mWhh_h);
    cudaGetSymbolAddress((void**)&mWhh_l, g_mWhh_l);

    float* h = atomfeat;   // h aliases atomfeat; updated in place by gru_combine

    // 0) weight prep
    {
        int n;
        n = 1800 * KPW; prep_pad_bf<<<(n + 255) / 256, 256>>>(Wih, Wih_h, Wih_l, 1800, DD);
        n = 1800 * KPW; prep_pad_bf<<<(n + 255) / 256, 256>>>(Whh, Whh_h, Whh_l, 1800, DD);
        n = 600 * KPW;  prep_pad_bf<<<(n + 255) / 256, 256>>>(mWih, mWih_h, mWih_l, 600, DD);
        n = 600 * KPW;  prep_pad_bf<<<(n + 255) / 256, 256>>>(mWhh, mWhh_h, mWhh_l, 600, DD);
        n = 200 * KPW;  prep_trans_bf<<<(n + 255) / 256, 256>>>(W_atom, WT_atom_h, WT_atom_l, 1, FAA, DD);
        n = 200 * KPW;  prep_trans_bf<<<(n + 255) / 256, 256>>>(W_nei, WT_nei_h, WT_nei_l, 1, FC, DD);
        n = 3 * 200 * KPW; prep_trans_bf<<<(n + 255) / 256, 256>>>(W_attend, WT_att_h, WT_att_l, 3, DD, DD);
        n = 200 * KPW;  prep_trans_bf<<<(n + 255) / 256, 256>>>(W_mol_att, WT_molatt_h, WT_molatt_l, 1, DD, DD);
    }

    // 1) atom_feature = lrelu(atom_list @ W_atom + b_atom)
    pad_atom_kernel<<<(NATOM * KPAD + 255) / 256, 256>>>(atom_list, atompad);
    tgemm(atompad, KPAD, KPAD, WT_atom_h, WT_atom_l, b_atom, nullptr, atomfeat, NATOM, DD, 1);

    // 2) nei0 = lrelu(concat @ W_nei + b_nei)
    build_concat<<<(NROWN * KPAD + 255) / 256, 256>>>(atom_list, bond_list, adeg, bdeg, concat);
    tgemm(concat, KPAD, KPAD, WT_nei_h, WT_nei_l, b_nei, nullptr, nei0, NROWN, DD, 1);

    // 3) atom GRU rounds
    for (int r = 0; r < RR; r++) {
        const float* curp = (r == 0) ? atomfeat : cur;
        ctx_kernel<<<NATOM / 8, 256>>>(curp, (r == 0) ? nei0 : nullptr, adeg,
                                       W_align + (size_t)r * D2, b_align + r,
                                       wsum, wtot, (r == 0) ? 1 : 0);
        tgemm(wsum, DD, DD, WT_att_h + (size_t)r * 200 * KPW, WT_att_l + (size_t)r * 200 * KPW,
              b_attend + r * DD, wtot, ctx, NATOM, DD, 2);
        tgemm_dual(ctx, Wih_h + (size_t)r * D3 * KPW, Wih_l + (size_t)r * D3 * KPW,
                   bih + r * D3, gi,
                   h, Whh_h + (size_t)r * D3 * KPW, Whh_l + (size_t)r * D3 * KPW,
                   bhh + r * D3, gh, NATOM, D3);
        gru_combine<<<(NATOM * DD + 255) / 256, 256>>>(gi, gh, h, h, cur, NATOM);
    }

    // 4) mol phase
    molprep_kernel<<<BDIM, 256>>>(cur, amask, W_mol_align, mol, actmol, s2);
    for (int t = 0; t < TTI; t++) {
        molctx_kernel<<<BDIM, 256>>>(actmol, cur, s2, amask, W_mol_align, b_mol_align,
                                     mwsum, mwtot);
        tgemm(mwsum, DD, DD, WT_molatt_h, WT_molatt_l, b_mol_att, mwtot, mctx, BDIM, DD, 2);
        tgemm_dual(mctx, mWih_h, mWih_l, mbih, mgi,
                   mol, mWhh_h, mWhh_l, mbhh, mgh, BDIM, D3);
        gru_combine<<<(BDIM * DD + 255) / 256, 256>>>(mgi, mgh, mol, mol, actmol, BDIM);
    }

    // 5) final projection
    final_kernel<<<BDIM, 256>>>(mol, W_metric, b_metric, W_out, b_out, (float*)d_out);
}

// round 15
// speedup vs baseline: 1.4565x; 1.0320x over previous
#include <cuda_runtime.h>
#include <cuda_bf16.h>
#include <math.h>
#include <stdint.h>

typedef unsigned long long u64;

#define BDIM 128
#define LDIM 128
#define NNEI 6
#define FAA 39
#define FBB 10
#define FC 49
#define DD 200
#define D2 400
#define D3 600
#define RR 3
#define TTI 2
#define MBOND 256
#define NEGV -9e8f
#define NATOM (BDIM*LDIM)    /* 16384 */
#define NROWN (NATOM*NNEI)   /* 98304 */
#define KPAD 64
#define KP 224
#define KPW (KP/2)           /* 112 pairs: stride for D=200 activations */
#define LDPA 32              /* pairs stride for K=64 inputs */
#define NPAIR 100            /* live pairs for D=200 */

// ---------------- device scratch (static, zero-initialized) ----------------
__device__ float g_atomfeat[NATOM*DD];   // h fp32 (updated in place)
__device__ float g_cur[NATOM*DD];
__device__ float g_nei0[NROWN*DD];
__device__ float g_gi[NATOM*D3];
__device__ float g_gh[NATOM*D3];
__device__ float g_wtot[NATOM];
__device__ float g_s2[NATOM];
__device__ float g_mol[BDIM*DD];
__device__ float g_actmol[BDIM*DD];
__device__ float g_mwtot[BDIM];
__device__ float g_mgi[BDIM*D3];
__device__ float g_mgh[BDIM*D3];
// packed activation planes (pads beyond NPAIR stay zero)
__device__ uint32_t g_apad_h[NATOM*LDPA],  g_apad_l[NATOM*LDPA];
__device__ uint32_t g_con_h[NROWN*LDPA],   g_con_l[NROWN*LDPA];
__device__ uint32_t g_h_h[NATOM*KPW],      g_h_l[NATOM*KPW];
__device__ uint32_t g_wsum_h[NATOM*KPW],   g_wsum_l[NATOM*KPW];
__device__ uint32_t g_ctx_h[NATOM*KPW],    g_ctx_l[NATOM*KPW];
__device__ uint32_t g_mol_h[BDIM*KPW],     g_mol_l[BDIM*KPW];
__device__ uint32_t g_mws_h[BDIM*KPW],     g_mws_l[BDIM*KPW];
__device__ uint32_t g_mctx_h[BDIM*KPW],    g_mctx_l[BDIM*KPW];
// packed bf16-pair weights
__device__ uint32_t g_WT_atom_h[200*KPW],  g_WT_atom_l[200*KPW];
__device__ uint32_t g_WT_nei_h[200*KPW],   g_WT_nei_l[200*KPW];
__device__ uint32_t g_WT_att_h[3*200*KPW], g_WT_att_l[3*200*KPW];
__device__ uint32_t g_WT_molatt_h[200*KPW],g_WT_molatt_l[200*KPW];
__device__ uint32_t g_Wih_h[3*600*KPW],    g_Wih_l[3*600*KPW];
__device__ uint32_t g_Whh_h[3*600*KPW],    g_Whh_l[3*600*KPW];
__device__ uint32_t g_mWih_h[600*KPW],     g_mWih_l[600*KPW];
__device__ uint32_t g_mWhh_h[600*KPW],     g_mWhh_l[600*KPW];

// ---------------- helpers ----------------
__device__ __forceinline__ float warpsum(float v) {
    #pragma unroll
    for (int o = 16; o > 0; o >>= 1) v += __shfl_down_sync(0xffffffffu, v, o);
    return v;
}
__device__ __forceinline__ float warpall(float v) {
    #pragma unroll
    for (int o = 16; o > 0; o >>= 1) v += __shfl_xor_sync(0xffffffffu, v, o);
    return v;
}
__device__ __forceinline__ float lrelu(float x) { return x > 0.f ? x : 0.01f * x; }
__device__ __forceinline__ float eluf(float x)  { return x > 0.f ? x : expm1f(x); }
__device__ __forceinline__ float sigm(float x)  { return 1.f / (1.f + expf(-x)); }

__device__ __forceinline__ void split_bf16(float x, __nv_bfloat16& h, __nv_bfloat16& l) {
    h = __float2bfloat16_rn(x);
    l = __float2bfloat16_rn(x - __bfloat162float(h));
}
__device__ __forceinline__ uint32_t pack2(__nv_bfloat16 a, __nv_bfloat16 b) {
    __nv_bfloat162 p = __halves2bfloat162(a, b);
    return *reinterpret_cast<uint32_t*>(&p);
}
// split two floats into packed hi/lo words
__device__ __forceinline__ void split_pair(float a, float b, uint32_t& hw, uint32_t& lw) {
    __nv_bfloat16 ha, la, hb, lb;
    split_bf16(a, ha, la); split_bf16(b, hb, lb);
    hw = pack2(ha, hb); lw = pack2(la, lb);
}

#define MMAB(c, a, b) \
    asm volatile("mma.sync.aligned.m16n8k16.row.col.f32.bf16.bf16.f32 " \
        "{%0,%1,%2,%3}, {%4,%5,%6,%7}, {%8,%9}, {%0,%1,%2,%3};" \
        : "+f"((c)[0]), "+f"((c)[1]), "+f"((c)[2]), "+f"((c)[3]) \
        : "r"((a)[0]), "r"((a)[1]), "r"((a)[2]), "r"((a)[3]), \
          "r"((b)[0]), "r"((b)[1]))

// =====================================================================
// Split-bf16 tensor GEMM, pre-packed A planes. BM=128 BN=128, prefetch.
// A: Aph/Apl [M, ldp] packed pairs. C: fp32 (if C) and/or packed (if Cph).
// DUAL=1: blockIdx.z==1 uses (A2h/A2l, W2h/W2l, bias2, C2-fp32).
// =====================================================================
template<int DUAL>
__global__ __launch_bounds__(256) void bfgemm_kernel(
    const uint32_t* __restrict__ Aph, const uint32_t* __restrict__ Apl, int ldp, int K,
    const uint32_t* __restrict__ WTh, const uint32_t* __restrict__ WTl,
    const float* __restrict__ bias,
    const float* __restrict__ rowscale,
    float* __restrict__ C, uint32_t* __restrict__ Cph, uint32_t* __restrict__ Cpl, int ldcp,
    int M, int Ntot, int act,
    const uint32_t* A2h, const uint32_t* A2l,
    const uint32_t* W2h, const uint32_t* W2l,
    const float* bias2, float* C2)
{
    if (DUAL && blockIdx.z == 1) {
        Aph = A2h; Apl = A2l; WTh = W2h; WTl = W2l; bias = bias2; C = C2;
    }

    __shared__ uint32_t APh[8][132], APl[8][132];
    __shared__ uint32_t BPh[8][136], BPl[8][136];

    const int tid = threadIdx.x;
    const int wid = tid >> 5;
    const int lane = tid & 31;
    const int gid = lane >> 2;
    const int tg = lane & 3;
    const int bm0 = blockIdx.x * 128;
    const int bn0 = blockIdx.y * 128;
    const int wm = (wid & 3) * 32;
    const int wn = (wid >> 2) * 64;

    const int a_r = tid >> 1, a_p4 = (tid & 1) << 2;   // A: 128 rows x 8 pairs
    const int b_r = tid >> 1, b_p4 = (tid & 1) << 2;   // B: 128 rows x 8 pairs

    float c[2][8][4];
    #pragma unroll
    for (int mt = 0; mt < 2; mt++)
        #pragma unroll
        for (int nt = 0; nt < 8; nt++)
            #pragma unroll
            for (int q = 0; q < 4; q++) c[mt][nt][q] = 0.f;

    const int nch = (K + 15) >> 4;

    uint4 avh, avl, bvh, bvl;
    {
        size_t aoff = (size_t)(bm0 + a_r) * ldp + a_p4;
        avh = *reinterpret_cast<const uint4*>(Aph + aoff);
        avl = *reinterpret_cast<const uint4*>(Apl + aoff);
        int n = bn0 + b_r;
        if (n < Ntot) {
            size_t off = (size_t)n * KPW + b_p4;
            bvh = *reinterpret_cast<const uint4*>(WTh + off);
            bvl = *reinterpret_cast<const uint4*>(WTl + off);
        } else { bvh = make_uint4(0u,0u,0u,0u); bvl = make_uint4(0u,0u,0u,0u); }
    }

    for (int chn = 0; chn < nch; chn++) {
        APh[a_p4 + 0][a_r] = avh.x; APh[a_p4 + 1][a_r] = avh.y;
        APh[a_p4 + 2][a_r] = avh.z; APh[a_p4 + 3][a_r] = avh.w;
        APl[a_p4 + 0][a_r] = avl.x; APl[a_p4 + 1][a_r] = avl.y;
        APl[a_p4 + 2][a_r] = avl.z; APl[a_p4 + 3][a_r] = avl.w;
        BPh[b_p4 + 0][b_r] = bvh.x; BPh[b_p4 + 1][b_r] = bvh.y;
        BPh[b_p4 + 2][b_r] = bvh.z; BPh[b_p4 + 3][b_r] = bvh.w;
        BPl[b_p4 + 0][b_r] = bvl.x; BPl[b_p4 + 1][b_r] = bvl.y;
        BPl[b_p4 + 2][b_r] = bvl.z; BPl[b_p4 + 3][b_r] = bvl.w;
        __syncthreads();

        if (chn + 1 < nch) {
            const int kp0 = (chn + 1) << 3;
            size_t aoff = (size_t)(bm0 + a_r) * ldp + kp0 + a_p4;
            avh = *reinterpret_cast<const uint4*>(Aph + aoff);
            avl = *reinterpret_cast<const uint4*>(Apl + aoff);
            int n = bn0 + b_r;
            if (n < Ntot) {
                size_t off = (size_t)n * KPW + kp0 + b_p4;
                bvh = *reinterpret_cast<const uint4*>(WTh + off);
                bvl = *reinterpret_cast<const uint4*>(WTl + off);
            } else { bvh = make_uint4(0u,0u,0u,0u); bvl = make_uint4(0u,0u,0u,0u); }
        }

        uint32_t ah[2][4], al[2][4];
        #pragma unroll
        for (int mt = 0; mt < 2; mt++) {
            int mr = wm + mt * 16;
            ah[mt][0] = APh[tg][mr + gid];
            ah[mt][1] = APh[tg][mr + gid + 8];
            ah[mt][2] = APh[tg + 4][mr + gid];
            ah[mt][3] = APh[tg + 4][mr + gid + 8];
            al[mt][0] = APl[tg][mr + gid];
            al[mt][1] = APl[tg][mr + gid + 8];
            al[mt][2] = APl[tg + 4][mr + gid];
            al[mt][3] = APl[tg + 4][mr + gid + 8];
        }
        #pragma unroll
        for (int nt = 0; nt < 8; nt++) {
            int nc = wn + nt * 8 + gid;
            uint32_t bh[2] = { BPh[tg][nc], BPh[tg + 4][nc] };
            uint32_t bl[2] = { BPl[tg][nc], BPl[tg + 4][nc] };
            #pragma unroll
            for (int mt = 0; mt < 2; mt++) {
                MMAB(c[mt][nt], ah[mt], bh);
                MMAB(c[mt][nt], ah[mt], bl);
                MMAB(c[mt][nt], al[mt], bh);
            }
        }
        __syncthreads();
    }

    #pragma unroll
    for (int mt = 0; mt < 2; mt++) {
        #pragma unroll
        for (int half = 0; half < 2; half++) {
            int m = bm0 + wm + mt * 16 + gid + half * 8;
            float rs = rowscale ? rowscale[m] : 1.f;
            #pragma unroll
            for (int nt = 0; nt < 8; nt++) {
                int n = bn0 + wn + nt * 8 + 2 * tg;
                if (n >= Ntot) continue;
                float v0 = c[mt][nt][half * 2 + 0] + rs * (bias ? bias[n] : 0.f);
                float v1 = c[mt][nt][half * 2 + 1] + rs * (bias ? bias[n + 1] : 0.f);
                if (act == 1) { v0 = lrelu(v0); v1 = lrelu(v1); }
                else if (act == 2) { v0 = eluf(v0); v1 = eluf(v1); }
                if (C) {
                    float* crow = C + (size_t)m * Ntot;
                    crow[n] = v0; crow[n + 1] = v1;
                }
                if (Cph) {
                    uint32_t hw, lw;
                    split_pair(v0, v1, hw, lw);
                    size_t po = (size_t)m * ldcp + (n >> 1);
                    Cph[po] = hw; Cpl[po] = lw;
                }
            }
        }
    }
}

// ---------------- weight prep: [NT,K] row-major -> packed hi/lo [NT,KPW] ----------------
__global__ void prep_pad_bf(const float* __restrict__ in,
                            uint32_t* __restrict__ outh, uint32_t* __restrict__ outl,
                            int NT, int K)
{
    int i = blockIdx.x * 256 + threadIdx.x;
    if (i >= NT * KPW) return;
    int n = i / KPW, kp = i - n * KPW;
    int k = kp << 1;
    float x0 = (k < K) ? in[(size_t)n * K + k] : 0.f;
    float x1 = (k + 1 < K) ? in[(size_t)n * K + k + 1] : 0.f;
    uint32_t hw, lw;
    split_pair(x0, x1, hw, lw);
    outh[i] = hw; outl[i] = lw;
}

// ---------------- weight prep: [R,K,N] -> packed hi/lo [R,N,KPW] ----------------
__global__ void prep_trans_bf(const float* __restrict__ in,
                              uint32_t* __restrict__ outh, uint32_t* __restrict__ outl,
                              int R, int K, int N)
{
    int i = blockIdx.x * 256 + threadIdx.x;
    if (i >= R * N * KPW) return;
    int kp = i % KPW;
    int rn = i / KPW;
    int n = rn % N;
    int r = rn / N;
    int k = kp << 1;
    float x0 = (k < K) ? in[((size_t)r * K + k) * N + n] : 0.f;
    float x1 = (k + 1 < K) ? in[((size_t)r * K + k + 1) * N + n] : 0.f;
    uint32_t hw, lw;
    split_pair(x0, x1, hw, lw);
    outh[i] = hw; outl[i] = lw;
}

// ---------------- pad atom_list -> packed [NATOM, LDPA] ----------------
__global__ void pad_atom_kernel(const float* __restrict__ atom_list,
                                uint32_t* __restrict__ outh, uint32_t* __restrict__ outl)
{
    int i = blockIdx.x * blockDim.x + threadIdx.x;
    if (i >= NATOM * LDPA) return;
    int row = i / LDPA;
    int p = i - row * LDPA;
    int k = p << 1;
    float x0 = (k < FAA) ? atom_list[row * FAA + k] : 0.f;
    float x1 = (k + 1 < FAA) ? atom_list[row * FAA + k + 1] : 0.f;
    uint32_t hw, lw;
    split_pair(x0, x1, hw, lw);
    outh[i] = hw; outl[i] = lw;
}

// ---------------- build concat packed [NROWN, LDPA] ----------------
__global__ void build_concat(const float* __restrict__ atom_list,
                             const float* __restrict__ bond_list,
                             const int* __restrict__ adeg,
                             const int* __restrict__ bdeg,
                             uint32_t* __restrict__ outh, uint32_t* __restrict__ outl)
{
    int i = blockIdx.x * blockDim.x + threadIdx.x;
    if (i >= NROWN * LDPA) return;
    int row = i / LDPA;
    int p = i - row * LDPA;
    int b = row / (LDIM * NNEI);
    int a = adeg[row];
    int bd = bdeg[row];
    const float* arow = atom_list + ((size_t)b * LDIM + a) * FAA;
    const float* brow = bond_list + ((size_t)b * MBOND + bd) * FBB;
    float v[2];
    #pragma unroll
    for (int q = 0; q < 2; q++) {
        int f = 2 * p + q;
        float x = 0.f;
        if (f < FAA) x = arow[f];
        else if (f < FC) x = brow[f - FAA];
        v[q] = x;
    }
    uint32_t hw, lw;
    split_pair(v[0], v[1], hw, lw);
    outh[i] = hw; outl[i] = lw;
}

// ---------------- attention: warp-per-atom, pair-based, packed wsum out ----------------
#define CHP 4   /* ceil(100/32) pair chunks */
__global__ void ctx_kernel(const float* __restrict__ cur,
                           const float* __restrict__ neiBuf,
                           const int* __restrict__ adeg,
                           const float* __restrict__ Wal,
                           const float* __restrict__ bal,
                           uint32_t* __restrict__ wsh, uint32_t* __restrict__ wsl,
                           float* __restrict__ wtot,
                           int firstRound)
{
    const int tid = threadIdx.x;
    const int wid = tid >> 5;
    const int lane = tid & 31;
    const int atom = blockIdx.x * 8 + wid;
    const int b = atom / LDIM;

    int myidx = (lane < NNEI) ? adeg[atom * NNEI + lane] : 0;
    int idx[NNEI];
    #pragma unroll
    for (int n = 0; n < NNEI; n++) idx[n] = __shfl_sync(0xffffffffu, myidx, n);

    const float* neirow[NNEI];
    #pragma unroll
    for (int n = 0; n < NNEI; n++)
        neirow[n] = firstRound ? (neiBuf + ((size_t)atom * NNEI + n) * DD)
                               : (cur + ((size_t)(b * LDIM + idx[n])) * DD);
    const float* currow = cur + (size_t)atom * DD;

    float2 curv[CHP], neiv[NNEI][CHP], w1v[CHP], w2v[CHP];
    #pragma unroll
    for (int i = 0; i < CHP; i++) {
        int p = lane + 32 * i;
        bool ok = p < NPAIR;
        int d = 2 * p;
        curv[i] = ok ? *reinterpret_cast<const float2*>(currow + d) : make_float2(0.f, 0.f);
        w1v[i]  = ok ? *reinterpret_cast<const float2*>(Wal + d) : make_float2(0.f, 0.f);
        w2v[i]  = ok ? *reinterpret_cast<const float2*>(Wal + DD + d) : make_float2(0.f, 0.f);
        #pragma unroll
        for (int n = 0; n < NNEI; n++)
            neiv[n][i] = ok ? *reinterpret_cast<const float2*>(neirow[n] + d)
                            : make_float2(0.f, 0.f);
    }

    float pc = 0.f;
    #pragma unroll
    for (int i = 0; i < CHP; i++) pc += w1v[i].x * curv[i].x + w1v[i].y * curv[i].y;
    pc = warpall(pc);
    float pn[NNEI];
    #pragma unroll
    for (int n = 0; n < NNEI; n++) {
        float p = 0.f;
        #pragma unroll
        for (int i = 0; i < CHP; i++) p += w2v[i].x * neiv[n][i].x + w2v[i].y * neiv[n][i].y;
        pn[n] = warpall(p);
    }

    float bb = bal[0];
    float sc[NNEI], msk[NNEI];
    float mx = -1e30f;
    #pragma unroll
    for (int n = 0; n < NNEI; n++) {
        float a = lrelu(pc + pn[n] + bb);
        bool pad = (idx[n] == LDIM - 1);
        msk[n] = pad ? 0.f : 1.f;
        a += pad ? NEGV : 0.f;
        sc[n] = a;
        mx = fmaxf(mx, a);
    }
    float sum = 0.f;
    float w[NNEI];
    #pragma unroll
    for (int n = 0; n < NNEI; n++) { w[n] = expf(sc[n] - mx); sum += w[n]; }
    float inv = 1.f / sum;
    float wt = 0.f;
    #pragma unroll
    for (int n = 0; n < NNEI; n++) { w[n] = w[n] * inv * msk[n]; wt += w[n]; }

    #pragma unroll
    for (int i = 0; i < CHP; i++) {
        int p = lane + 32 * i;
        if (p < NPAIR) {
            float s0 = 0.f, s1 = 0.f;
            #pragma unroll
            for (int n = 0; n < NNEI; n++) {
                s0 += w[n] * neiv[n][i].x;
                s1 += w[n] * neiv[n][i].y;
            }
            uint32_t hw, lw;
            split_pair(s0, s1, hw, lw);
            size_t po = (size_t)atom * KPW + p;
            wsh[po] = hw; wsl[po] = lw;
        }
    }
    if (lane == 0) wtot[atom] = wt;
}

// ---------------- GRU combine (pair-based; writes h fp32+packed, act fp32) ----------------
__global__ void gru_combine(const float* __restrict__ gi, const float* __restrict__ gh,
                            const float* __restrict__ h,
                            float* __restrict__ hOut,
                            uint32_t* __restrict__ hPh, uint32_t* __restrict__ hPl,
                            float* __restrict__ actOut, int Mrows)
{
    int i = blockIdx.x * blockDim.x + threadIdx.x;
    if (i >= Mrows * NPAIR) return;
    int m = i / NPAIR;
    int p = i - m * NPAIR;
    int d = 2 * p;
    const float* gim = gi + (size_t)m * D3;
    const float* ghm = gh + (size_t)m * D3;
    float hn[2];
    #pragma unroll
    for (int q = 0; q < 2; q++) {
        int dq = d + q;
        float r = sigm(gim[dq] + ghm[dq]);
        float z = sigm(gim[DD + dq] + ghm[DD + dq]);
        float nv = tanhf(gim[2 * DD + dq] + r * ghm[2 * DD + dq]);
        float hv = h[(size_t)m * DD + dq];
        hn[q] = (1.f - z) * nv + z * hv;
        hOut[(size_t)m * DD + dq] = hn[q];
        actOut[(size_t)m * DD + dq] = hn[q] > 0.f ? hn[q] : 0.f;
    }
    uint32_t hw, lw;
    split_pair(hn[0], hn[1], hw, lw);
    size_t po = (size_t)m * KPW + p;
    hPh[po] = hw; hPl[po] = lw;
}

// ---------------- mol prep: masked sum (+packed mol) + per-atom s2 dot ----------------
__global__ void molprep_kernel(const float* __restrict__ cur, const float* __restrict__ amask,
                               const float* __restrict__ Wma,
                               float* __restrict__ mol,
                               uint32_t* __restrict__ molPh, uint32_t* __restrict__ molPl,
                               float* __restrict__ actmol,
                               float* __restrict__ s2)
{
    int b = blockIdx.x;
    int tid = threadIdx.x;
    for (int p = tid; p < NPAIR; p += 256) {
        int d = 2 * p;
        float s0 = 0.f, s1 = 0.f;
        for (int l = 0; l < LDIM; l++) {
            float am = amask[b * LDIM + l];
            const float* row = cur + ((size_t)b * LDIM + l) * DD + d;
            s0 += row[0] * am;
            s1 += row[1] * am;
        }
        mol[b * DD + d] = s0;
        mol[b * DD + d + 1] = s1;
        actmol[b * DD + d] = s0 > 0.f ? s0 : 0.f;
        actmol[b * DD + d + 1] = s1 > 0.f ? s1 : 0.f;
        uint32_t hw, lw;
        split_pair(s0, s1, hw, lw);
        molPh[(size_t)b * KPW + p] = hw;
        molPl[(size_t)b * KPW + p] = lw;
    }
    int w = tid >> 5;
    int lane = tid & 31;
    for (int l = w; l < LDIM; l += 8) {
        float p = 0.f;
        const float* row = cur + ((size_t)b * LDIM + l) * DD;
        for (int d = lane; d < DD; d += 32) p += row[d] * Wma[DD + d];
        p = warpsum(p);
        if (lane == 0) s2[b * LDIM + l] = p;
    }
}

// ---------------- mol attention: packed mwsum out ----------------
__global__ void molctx_kernel(const float* __restrict__ actmol,
                              const float* __restrict__ cur,
                              const float* __restrict__ s2,
                              const float* __restrict__ amask,
                              const float* __restrict__ Wma,
                              const float* __restrict__ bma,
                              uint32_t* __restrict__ mwsh, uint32_t* __restrict__ mwsl,
                              float* __restrict__ mwtot)
{
    int b = blockIdx.x;
    int tid = threadIdx.x;
    int lane = tid & 31;
    __shared__ float redv;
    __shared__ float sc[LDIM];
    __shared__ float wS[LDIM];
    if (tid == 0) redv = 0.f;
    __syncthreads();

    float p = 0.f;
    for (int d = tid; d < DD; d += 256) p += actmol[b * DD + d] * Wma[d];
    p = warpsum(p);
    if (lane == 0) atomicAdd(&redv, p);
    __syncthreads();

    if (tid < LDIM) {
        float a = lrelu(redv + s2[b * LDIM + tid] + bma[0]);
        if (amask[b * LDIM + tid] == 0.f) a += NEGV;
        sc[tid] = a;
    }
    __syncthreads();

    float mx = -1e30f;
    for (int l = 0; l < LDIM; l++) mx = fmaxf(mx, sc[l]);
    float sum = 0.f;
    for (int l = 0; l < LDIM; l++) sum += expf(sc[l] - mx);
    float inv = 1.f / sum;
    if (tid < LDIM) wS[tid] = expf(sc[tid] - mx) * inv * amask[b * LDIM + tid];
    __syncthreads();

    for (int pp = tid; pp < NPAIR; pp += 256) {
        int d = 2 * pp;
        float s0 = 0.f, s1 = 0.f;
        for (int l = 0; l < LDIM; l++) {
            const float* row = cur + ((size_t)b * LDIM + l) * DD + d;
            s0 += wS[l] * row[0];
            s1 += wS[l] * row[1];
        }
        uint32_t hw, lw;
        split_pair(s0, s1, hw, lw);
        mwsh[(size_t)b * KPW + pp] = hw;
        mwsl[(size_t)b * KPW + pp] = lw;
    }
    if (tid == 0) {
        float wt = 0.f;
        for (int l = 0; l < LDIM; l++) wt += wS[l];
        mwtot[b] = wt;
    }
}

// ---------------- final projection ----------------
__global__ void final_kernel(const float* __restrict__ mol,
                             const float* __restrict__ Wm, const float* __restrict__ bm,
                             const float* __restrict__ Wo, const float* __restrict__ bo,
                             float* __restrict__ out)
{
    int b = blockIdx.x;
    int tid = threadIdx.x;
    int lane = tid & 31;
    __shared__ float featS[D2];
    __shared__ float ws[8];
    for (int j = tid; j < D2; j += 256)
        featS[j] = (j < DD) ? mol[b * DD + j] : (mol[b * DD + j - DD] + (float)(RR - 2));
    __syncthreads();
    float p = 0.f;
    for (int d = tid; d < DD; d += 256) {
        float s = bm[d];
        for (int j = 0; j < D2; j++) s += featS[j] * Wm[j * DD + d];
        p += s * Wo[d];
    }
    p = warpsum(p);
    if (lane == 0) ws[tid >> 5] = p;
    __syncthreads();
    if (tid == 0) {
        float t = 0.f;
        for (int i = 0; i < 8; i++) t += ws[i];
        out[b] = t + bo[0];
    }
}

// ---------------- host-side dispatch ----------------
static void tgemm(const uint32_t* Aph, const uint32_t* Apl, int ldp, int K,
                  const uint32_t* WTh, const uint32_t* WTl,
                  const float* bias, const float* rowscale,
                  float* C, uint32_t* Cph, uint32_t* Cpl,
                  int M, int Ntot, int act)
{
    dim3 g(M / 128, (Ntot + 127) / 128, 1);
    bfgemm_kernel<0><<<g, 256>>>(Aph, Apl, ldp, K, WTh, WTl, bias, rowscale,
                                 C, Cph, Cpl, KPW, M, Ntot, act,
                                 nullptr, nullptr, nullptr, nullptr, nullptr, nullptr);
}

static void tgemm_dual(const uint32_t* A1h, const uint32_t* A1l,
                       const uint32_t* W1h, const uint32_t* W1l,
                       const float* bias1, float* C1,
                       const uint32_t* A2h, const uint32_t* A2l,
                       const uint32_t* W2h, const uint32_t* W2l,
                       const float* bias2, float* C2,
                       int M, int Ntot)
{
    dim3 g(M / 128, (Ntot + 127) / 128, 2);
    bfgemm_kernel<1><<<g, 256>>>(A1h, A1l, KPW, DD, W1h, W1l, bias1, nullptr,
                                 C1, nullptr, nullptr, KPW, M, Ntot, 0,
                                 A2h, A2l, W2h, W2l, bias2, C2);
}

extern "C" void kernel_launch(void* const* d_in, const int* in_sizes, int n_in,
                              void* d_out, int out_size)
{
    const float* atom_list   = (const float*)d_in[0];
    const float* bond_list   = (const float*)d_in[1];
    const int*   adeg        = (const int*)d_in[2];
    const int*   bdeg        = (const int*)d_in[3];
    const float* amask       = (const float*)d_in[4];
    const float* W_atom      = (const float*)d_in[5];
    const float* b_atom      = (const float*)d_in[6];
    const float* W_nei       = (const float*)d_in[7];
    const float* b_nei       = (const float*)d_in[8];
    const float* W_align     = (const float*)d_in[9];
    const float* b_align     = (const float*)d_in[10];
    const float* W_attend    = (const float*)d_in[11];
    const float* b_attend    = (const float*)d_in[12];
    const float* Wih         = (const float*)d_in[13];
    const float* Whh         = (const float*)d_in[14];
    const float* bih         = (const float*)d_in[15];
    const float* bhh         = (const float*)d_in[16];
    const float* W_mol_align = (const float*)d_in[17];
    const float* b_mol_align = (const float*)d_in[18];
    const float* W_mol_att   = (const float*)d_in[19];
    const float* b_mol_att   = (const float*)d_in[20];
    const float* mWih        = (const float*)d_in[21];
    const float* mWhh        = (const float*)d_in[22];
    const float* mbih        = (const float*)d_in[23];
    const float* mbhh        = (const float*)d_in[24];
    const float* W_metric    = (const float*)d_in[25];
    const float* b_metric    = (const float*)d_in[26];
    const float* W_out       = (const float*)d_in[27];
    const float* b_out       = (const float*)d_in[28];

    float *atomfeat, *cur, *nei0, *gi, *gh, *wtot, *s2, *mol, *actmol, *mwtot, *mgi, *mgh;
    uint32_t *apad_h, *apad_l, *con_h, *con_l, *h_h, *h_l, *wsum_h, *wsum_l;
    uint32_t *ctx_h, *ctx_l, *mol_h, *mol_l, *mws_h, *mws_l, *mctx_h, *mctx_l;
    uint32_t *WT_atom_h, *WT_atom_l, *WT_nei_h, *WT_nei_l, *WT_att_h, *WT_att_l;
    uint32_t *WT_molatt_h, *WT_molatt_l, *Wih_h, *Wih_l, *Whh_h, *Whh_l;
    uint32_t *mWih_h, *mWih_l, *mWhh_h, *mWhh_l;
    cudaGetSymbolAddress((void**)&atomfeat, g_atomfeat);
    cudaGetSymbolAddress((void**)&cur, g_cur);
    cudaGetSymbolAddress((void**)&nei0, g_nei0);
    cudaGetSymbolAddress((void**)&gi, g_gi);
    cudaGetSymbolAddress((void**)&gh, g_gh);
    cudaGetSymbolAddress((void**)&wtot, g_wtot);
    cudaGetSymbolAddress((void**)&s2, g_s2);
    cudaGetSymbolAddress((void**)&mol, g_mol);
    cudaGetSymbolAddress((void**)&actmol, g_actmol);
    cudaGetSymbolAddress((void**)&mwtot, g_mwtot);
    cudaGetSymbolAddress((void**)&mgi, g_mgi);
    cudaGetSymbolAddress((void**)&mgh, g_mgh);
    cudaGetSymbolAddress((void**)&apad_h, g_apad_h);
    cudaGetSymbolAddress((void**)&apad_l, g_apad_l);
    cudaGetSymbolAddress((void**)&con_h, g_con_h);
    cudaGetSymbolAddress((void**)&con_l, g_con_l);
    cudaGetSymbolAddress((void**)&h_h, g_h_h);
    cudaGetSymbolAddress((void**)&h_l, g_h_l);
    cudaGetSymbolAddress((void**)&wsum_h, g_wsum_h);
    cudaGetSymbolAddress((void**)&wsum_l, g_wsum_l);
    cudaGetSymbolAddress((void**)&ctx_h, g_ctx_h);
    cudaGetSymbolAddress((void**)&ctx_l, g_ctx_l);
    cudaGetSymbolAddress((void**)&mol_h, g_mol_h);
    cudaGetSymbolAddress((void**)&mol_l, g_mol_l);
    cudaGetSymbolAddress((void**)&mws_h, g_mws_h);
    cudaGetSymbolAddress((void**)&mws_l, g_mws_l);
    cudaGetSymbolAddress((void**)&mctx_h, g_mctx_h);
    cudaGetSymbolAddress((void**)&mctx_l, g_mctx_l);
    cudaGetSymbolAddress((void**)&WT_atom_h, g_WT_atom_h);
    cudaGetSymbolAddress((void**)&WT_atom_l, g_WT_atom_l);
    cudaGetSymbolAddress((void**)&WT_nei_h, g_WT_nei_h);
    cudaGetSymbolAddress((void**)&WT_nei_l, g_WT_nei_l);
    cudaGetSymbolAddress((void**)&WT_att_h, g_WT_att_h);
    cudaGetSymbolAddress((void**)&WT_att_l, g_WT_att_l);
    cudaGetSymbolAddress((void**)&WT_molatt_h, g_WT_molatt_h);
    cudaGetSymbolAddress((void**)&WT_molatt_l, g_WT_molatt_l);
    cudaGetSymbolAddress((void**)&Wih_h, g_Wih_h);
    cudaGetSymbolAddress((void**)&Wih_l, g_Wih_l);
    cudaGetSymbolAddress((void**)&Whh_h, g_Whh_h);
    cudaGetSymbolAddress((void**)&Whh_l, g_Whh_l);
    cudaGetSymbolAddress((void**)&mWih_h, g_mWih_h);
    cudaGetSymbolAddress((void**)&mWih_l, g_mWih_l);
    cudaGetSymbolAddress((void**)&mWhh_h, g_mWhh_h);
    cudaGetSymbolAddress((void**)&mWhh_l, g_mWhh_l);

    float* h = atomfeat;   // h fp32 aliases atomfeat

    // 0) weight prep
    {
        int n;
        n = 1800 * KPW; prep_pad_bf<<<(n + 255) / 256, 256>>>(Wih, Wih_h, Wih_l, 1800, DD);
        n = 1800 * KPW; prep_pad_bf<<<(n + 255) / 256, 256>>>(Whh, Whh_h, Whh_l, 1800, DD);
        n = 600 * KPW;  prep_pad_bf<<<(n + 255) / 256, 256>>>(mWih, mWih_h, mWih_l, 600, DD);
        n = 600 * KPW;  prep_pad_bf<<<(n + 255) / 256, 256>>>(mWhh, mWhh_h, mWhh_l, 600, DD);
        n = 200 * KPW;  prep_trans_bf<<<(n + 255) / 256, 256>>>(W_atom, WT_atom_h, WT_atom_l, 1, FAA, DD);
        n = 200 * KPW;  prep_trans_bf<<<(n + 255) / 256, 256>>>(W_nei, WT_nei_h, WT_nei_l, 1, FC, DD);
        n = 3 * 200 * KPW; prep_trans_bf<<<(n + 255) / 256, 256>>>(W_attend, WT_att_h, WT_att_l, 3, DD, DD);
        n = 200 * KPW;  prep_trans_bf<<<(n + 255) / 256, 256>>>(W_mol_att, WT_molatt_h, WT_molatt_l, 1, DD, DD);
    }

    // 1) atom_feature = lrelu(atom_list @ W_atom + b_atom)  (fp32 + packed h0)
    pad_atom_kernel<<<(NATOM * LDPA + 255) / 256, 256>>>(atom_list, apad_h, apad_l);
    tgemm(apad_h, apad_l, LDPA, KPAD, WT_atom_h, WT_atom_l, b_atom, nullptr,
          atomfeat, h_h, h_l, NATOM, DD, 1);

    // 2) nei0 = lrelu(concat @ W_nei + b_nei)  (fp32, consumed by ctx round 0)
    build_concat<<<(NROWN * LDPA + 255) / 256, 256>>>(atom_list, bond_list, adeg, bdeg,
                                                      con_h, con_l);
    tgemm(con_h, con_l, LDPA, KPAD, WT_nei_h, WT_nei_l, b_nei, nullptr,
          nei0, nullptr, nullptr, NROWN, DD, 1);

    // 3) atom GRU rounds
    for (int r = 0; r < RR; r++) {
        const float* curp = (r == 0) ? atomfeat : cur;
        ctx_kernel<<<NATOM / 8, 256>>>(curp, (r == 0) ? nei0 : nullptr, adeg,
                                       W_align + (size_t)r * D2, b_align + r,
                                       wsum_h, wsum_l, wtot, (r == 0) ? 1 : 0);
        tgemm(wsum_h, wsum_l, KPW, DD,
              WT_att_h + (size_t)r * 200 * KPW, WT_att_l + (size_t)r * 200 * KPW,
              b_attend + r * DD, wtot, nullptr, ctx_h, ctx_l, NATOM, DD, 2);
        tgemm_dual(ctx_h, ctx_l, Wih_h + (size_t)r * D3 * KPW, Wih_l + (size_t)r * D3 * KPW,
                   bih + r * D3, gi,
                   h_h, h_l, Whh_h + (size_t)r * D3 * KPW, Whh_l + (size_t)r * D3 * KPW,
                   bhh + r * D3, gh, NATOM, D3);
        gru_combine<<<(NATOM * NPAIR + 255) / 256, 256>>>(gi, gh, h, h, h_h, h_l, cur, NATOM);
    }

    // 4) mol phase
    molprep_kernel<<<BDIM, 256>>>(cur, amask, W_mol_align, mol, mol_h, mol_l, actmol, s2);
    for (int t = 0; t < TTI; t++) {
        molctx_kernel<<<BDIM, 256>>>(actmol, cur, s2, amask, W_mol_align, b_mol_align,
                                     mws_h, mws_l, mwtot);
        tgemm(mws_h, mws_l, KPW, DD, WT_molatt_h, WT_molatt_l, b_mol_att, mwtot,
              nullptr, mctx_h, mctx_l, BDIM, DD, 2);
        tgemm_dual(mctx_h, mctx_l, mWih_h, mWih_l, mbih, mgi,
                   mol_h, mol_l, mWhh_h, mWhh_l, mbhh, mgh, BDIM, D3);
        gru_combine<<<(BDIM * NPAIR + 255) / 256, 256>>>(mgi, mgh, mol, mol, mol_h, mol_l,
                                                         actmol, BDIM);
    }

    // 5) final projection
    final_kernel<<<BDIM, 256>>>(mol, W_metric, b_metric, W_out, b_out, (float*)d_out);
}